// round 3
// baseline (speedup 1.0000x reference)
#include <cuda_runtime.h>
#include <math.h>

#define NV   7
#define CIN  512
#define HH   64
#define WW   112
#define HWSZ (HH*WW)      // 7168
#define DM   128
#define PP   36864
#define VD   4
#define VH   96
#define VW   96
#define OC   64
#define BNEPS 1e-5f

// ---------------- scratch (device globals; no allocations) ----------------
__device__ float g_feat[NV * HWSZ * DM];   // [n][hw][d]   25.7 MB
__device__ float g_fused[PP * DM];         // [p][c]       18.9 MB
__device__ float g_h2[PP * DM];            // [voxel][c]   18.9 MB (channel-last z,y,x,c)
__device__ float g_h3[PP * OC];            // [voxel][o]    9.4 MB
__device__ float g_wt[5*5*DM*5*OC];        // [kd][kh][c][kw][o]  4.1 MB

// ---------------- Kernel 1: projection GEMM + BN1 + ReLU ----------------
// feat[m][d] = relu(bn1( sum_k img[n][k][hw] * wproj[d][k] + bproj[d] ))
// m = n*7168 + hw, M=50176, K=512, N=128.  BM=64, BN=128, BK=16, 128 threads.
__global__ __launch_bounds__(128) void k1_proj(
    const float* __restrict__ img, const float* __restrict__ wproj,
    const float* __restrict__ bproj,
    const float* __restrict__ g1, const float* __restrict__ bb1,
    const float* __restrict__ m1, const float* __restrict__ v1)
{
    __shared__ __align__(16) float As[16][64];
    __shared__ __align__(16) float Bs[16][128];

    const int m0  = blockIdx.x * 64;
    const int n   = m0 / HWSZ;          // tile never crosses view boundary (7168%64==0)
    const int hw0 = m0 % HWSZ;
    const int tid = threadIdx.x;
    const int tx = tid & 15, ty = tid >> 4;   // c0 = tx*8, r0 = ty*8
    const int r0 = ty * 8, c0 = tx * 8;

    float acc[8][8];
    #pragma unroll
    for (int r = 0; r < 8; r++)
        #pragma unroll
        for (int c = 0; c < 8; c++) acc[r][c] = 0.f;

    const int li = tid & 63;
    const int jg = tid >> 6;

    for (int k0 = 0; k0 < CIN; k0 += 16) {
        __syncthreads();
        // A tile: [64 m][16 k], gmem coalesced along m
        {
            const float* Ab = img + ((size_t)n * CIN + k0 + jg * 8) * HWSZ + hw0 + li;
            #pragma unroll
            for (int jj = 0; jj < 8; jj++)
                As[jg * 8 + jj][li] = Ab[(size_t)jj * HWSZ];
        }
        // B tile: Bs[k][d] = wproj[d][k0+k]
        {
            const float* Bb = wproj + (size_t)tid * CIN + k0;
            #pragma unroll
            for (int jj = 0; jj < 16; jj += 4) {
                float4 t = *(const float4*)(Bb + jj);
                Bs[jj    ][tid] = t.x;
                Bs[jj + 1][tid] = t.y;
                Bs[jj + 2][tid] = t.z;
                Bs[jj + 3][tid] = t.w;
            }
        }
        __syncthreads();
        #pragma unroll
        for (int j = 0; j < 16; j++) {
            float a[8], b[8];
            *(float4*)(a)     = *(const float4*)&As[j][r0];
            *(float4*)(a + 4) = *(const float4*)&As[j][r0 + 4];
            *(float4*)(b)     = *(const float4*)&Bs[j][c0];
            *(float4*)(b + 4) = *(const float4*)&Bs[j][c0 + 4];
            #pragma unroll
            for (int r = 0; r < 8; r++)
                #pragma unroll
                for (int c = 0; c < 8; c++)
                    acc[r][c] += a[r] * b[c];
        }
    }

    // epilogue: bias + BN1 + ReLU
    float sc[8], sh[8];
    #pragma unroll
    for (int c = 0; c < 8; c++) {
        int d = c0 + c;
        float s = g1[d] * rsqrtf(v1[d] + BNEPS);
        sc[c] = s;
        sh[c] = (bproj[d] - m1[d]) * s + bb1[d];
    }
    #pragma unroll
    for (int r = 0; r < 8; r++) {
        float o[8];
        #pragma unroll
        for (int c = 0; c < 8; c++)
            o[c] = fmaxf(acc[r][c] * sc[c] + sh[c], 0.f);
        float* dst = &g_feat[(size_t)(m0 + r0 + r) * DM + c0];
        *(float4*)(dst)     = *(float4*)(o);
        *(float4*)(dst + 4) = *(float4*)(o + 4);
    }
}

// ---------------- Kernel 2: gather + masked softmax fusion ----------------
// one block per p (128 threads = d), 7 views in registers
// NOTE: valid is int32 (harness materializes bool as int32)
__global__ __launch_bounds__(128) void k2_fuse(
    const int* __restrict__ xi, const int* __restrict__ yi,
    const int* __restrict__ valid)
{
    const int p = blockIdx.x;
    const int d = threadIdx.x;
    float vv[NV];
    #pragma unroll
    for (int n = 0; n < NV; n++) {
        float val = 0.f;
        if (valid[n * PP + p]) {   // uniform per block
            int lin = yi[n * PP + p] * WW + xi[n * PP + p];
            val = g_feat[((size_t)(n * HWSZ + lin)) * DM + d];
        }
        vv[n] = val;
    }
    float mx = vv[0];
    #pragma unroll
    for (int n = 1; n < NV; n++) mx = fmaxf(mx, vv[n]);
    float s = 0.f, ws = 0.f;
    #pragma unroll
    for (int n = 0; n < NV; n++) {
        float e = expf(vv[n] - mx);
        s += e;
        ws += e * vv[n];
    }
    g_fused[(size_t)p * DM + d] = ws / s;
}

// ---------------- Kernel 3: 1x1 GEMM (128->128) + BN2 + ReLU ----------------
// h2[p][o] = relu(bn2( sum_c fused[p][c]*w3a[o][c] + b3a[o] )), M=36864,K=128,N=128
__global__ __launch_bounds__(128) void k3_mix(
    const float* __restrict__ w3a, const float* __restrict__ b3a,
    const float* __restrict__ g2, const float* __restrict__ bb2,
    const float* __restrict__ m2, const float* __restrict__ v2)
{
    __shared__ __align__(16) float As[16][64];
    __shared__ __align__(16) float Bs[16][128];

    const int m0  = blockIdx.x * 64;
    const int tid = threadIdx.x;
    const int tx = tid & 15, ty = tid >> 4;
    const int r0 = ty * 8, c0 = tx * 8;

    float acc[8][8];
    #pragma unroll
    for (int r = 0; r < 8; r++)
        #pragma unroll
        for (int c = 0; c < 8; c++) acc[r][c] = 0.f;

    const int mm = tid & 63;
    const int j0 = (tid >> 6) * 8;

    for (int k0 = 0; k0 < DM; k0 += 16) {
        __syncthreads();
        {
            const float* Ab = g_fused + (size_t)(m0 + mm) * DM + k0 + j0;
            float4 t0 = *(const float4*)Ab;
            float4 t1 = *(const float4*)(Ab + 4);
            As[j0    ][mm] = t0.x; As[j0 + 1][mm] = t0.y;
            As[j0 + 2][mm] = t0.z; As[j0 + 3][mm] = t0.w;
            As[j0 + 4][mm] = t1.x; As[j0 + 5][mm] = t1.y;
            As[j0 + 6][mm] = t1.z; As[j0 + 7][mm] = t1.w;
        }
        {
            const float* Bb = w3a + (size_t)tid * DM + k0;
            #pragma unroll
            for (int jj = 0; jj < 16; jj += 4) {
                float4 t = *(const float4*)(Bb + jj);
                Bs[jj    ][tid] = t.x;
                Bs[jj + 1][tid] = t.y;
                Bs[jj + 2][tid] = t.z;
                Bs[jj + 3][tid] = t.w;
            }
        }
        __syncthreads();
        #pragma unroll
        for (int j = 0; j < 16; j++) {
            float a[8], b[8];
            *(float4*)(a)     = *(const float4*)&As[j][r0];
            *(float4*)(a + 4) = *(const float4*)&As[j][r0 + 4];
            *(float4*)(b)     = *(const float4*)&Bs[j][c0];
            *(float4*)(b + 4) = *(const float4*)&Bs[j][c0 + 4];
            #pragma unroll
            for (int r = 0; r < 8; r++)
                #pragma unroll
                for (int c = 0; c < 8; c++)
                    acc[r][c] += a[r] * b[c];
        }
    }

    float sc[8], sh[8];
    #pragma unroll
    for (int c = 0; c < 8; c++) {
        int d = c0 + c;
        float s = g2[d] * rsqrtf(v2[d] + BNEPS);
        sc[c] = s;
        sh[c] = (b3a[d] - m2[d]) * s + bb2[d];
    }
    #pragma unroll
    for (int r = 0; r < 8; r++) {
        float o[8];
        #pragma unroll
        for (int c = 0; c < 8; c++)
            o[c] = fmaxf(acc[r][c] * sc[c] + sh[c], 0.f);
        float* dst = &g_h2[(size_t)(m0 + r0 + r) * DM + c0];
        *(float4*)(dst)     = *(float4*)(o);
        *(float4*)(dst + 4) = *(float4*)(o + 4);
    }
}

// ---------------- weight transpose: w3b[o][c][kd][kh][kw] -> [kd][kh][c][kw][o] ----
__global__ void k_wt(const float* __restrict__ w3b)
{
    int idx = blockIdx.x * 256 + threadIdx.x;
    const int TOT = OC * DM * 125;
    if (idx >= TOT) return;
    int kw = idx % 5;
    int kh = (idx / 5) % 5;
    int kd = (idx / 25) % 5;
    int c  = (idx / 125) % DM;
    int o  = idx / (125 * DM);
    g_wt[((((size_t)(kd * 5 + kh) * DM + c) * 5 + kw) * OC) + o] = w3b[idx];
}

// ---------------- Kernel 4: direct 5x5x5 conv (128->64) + BN3 + ReLU ----------
// grid (6,6,4): 16x16 (y,x) tile, one z slice, all 64 oc.
// thread = 8 consecutive x * 8 oc -> 64 fp32 accumulators.
__global__ __launch_bounds__(256) void k4_conv(
    const float* __restrict__ b3b,
    const float* __restrict__ g3, const float* __restrict__ bb3,
    const float* __restrict__ m3, const float* __restrict__ v3)
{
    __shared__ __align__(16) float s_in[VD][4][20][28];  // [z][c][y][x-pad]
    __shared__ __align__(16) float s_w[4][5][OC];        // [c][kw][o]

    const int z  = blockIdx.z;
    const int by = blockIdx.y * 16, bx = blockIdx.x * 16;
    const int tid = threadIdx.x;
    const int og  = tid >> 5;             // oc group (8 oc)
    const int sp  = tid & 31;
    const int ly  = sp >> 1;              // 0..15
    const int lxh = (sp & 1) << 3;        // 0 or 8

    float acc[8][8];
    #pragma unroll
    for (int j = 0; j < 8; j++)
        #pragma unroll
        for (int o = 0; o < 8; o++) acc[j][o] = 0.f;

    for (int cb = 0; cb < DM; cb += 4) {
        __syncthreads();
        // stage input tile (4 channels, all z, 20x20 halo), float4 per (z,y,x)
        #pragma unroll 1
        for (int i = tid; i < VD * 20 * 20; i += 256) {
            int xx = i % 20;
            int yy = (i / 20) % 20;
            int zz = i / 400;
            int gy = by + yy - 2, gx = bx + xx - 2;
            float4 val = make_float4(0.f, 0.f, 0.f, 0.f);
            if ((unsigned)gy < VH && (unsigned)gx < VW)
                val = *(const float4*)&g_h2[(((size_t)zz * VH + gy) * VW + gx) * DM + cb];
            s_in[zz][0][yy][xx] = val.x;
            s_in[zz][1][yy][xx] = val.y;
            s_in[zz][2][yy][xx] = val.z;
            s_in[zz][3][yy][xx] = val.w;
        }
        __syncthreads();

        #pragma unroll 1
        for (int kd = 0; kd < 5; kd++) {
            int zi = z + kd - 2;
            if ((unsigned)zi >= VD) continue;   // uniform over block
            #pragma unroll 1
            for (int kh = 0; kh < 5; kh++) {
                __syncthreads();
                // stage weights [4c][5kw][64o]: fully contiguous in g_wt
                const float* wsrc = g_wt + ((size_t)(kd * 5 + kh) * DM + cb) * 5 * OC;
                #pragma unroll 1
                for (int i = tid; i < 4 * 5 * OC; i += 256)
                    ((float*)s_w)[i] = wsrc[i];
                __syncthreads();

                #pragma unroll
                for (int c = 0; c < 4; c++) {
                    const float* row = &s_in[zi][c][ly + kh][lxh];
                    float r[12];
                    float4 t;
                    t = *(const float4*)(row);     r[0]=t.x; r[1]=t.y; r[2]=t.z; r[3]=t.w;
                    t = *(const float4*)(row + 4); r[4]=t.x; r[5]=t.y; r[6]=t.z; r[7]=t.w;
                    t = *(const float4*)(row + 8); r[8]=t.x; r[9]=t.y; r[10]=t.z; r[11]=t.w;
                    #pragma unroll
                    for (int kw = 0; kw < 5; kw++) {
                        float4 w0 = *(const float4*)&s_w[c][kw][og * 8];
                        float4 w1 = *(const float4*)&s_w[c][kw][og * 8 + 4];
                        float wr[8] = {w0.x, w0.y, w0.z, w0.w, w1.x, w1.y, w1.z, w1.w};
                        #pragma unroll
                        for (int j = 0; j < 8; j++) {
                            float iv = r[j + kw];
                            #pragma unroll
                            for (int o = 0; o < 8; o++)
                                acc[j][o] += iv * wr[o];
                        }
                    }
                }
            }
        }
    }

    // epilogue: + b3b, BN3, ReLU -> g_h3[voxel][oc]
    const int obase = og * 8;
    float sc[8], sh[8];
    #pragma unroll
    for (int o = 0; o < 8; o++) {
        int oc = obase + o;
        float s = g3[oc] * rsqrtf(v3[oc] + BNEPS);
        sc[o] = s;
        sh[o] = (b3b[oc] - m3[oc]) * s + bb3[oc];
    }
    const size_t vox0 = ((size_t)z * VH + by + ly) * VW + bx + lxh;
    #pragma unroll
    for (int j = 0; j < 8; j++) {
        float o[8];
        #pragma unroll
        for (int k = 0; k < 8; k++)
            o[k] = fmaxf(acc[j][k] * sc[k] + sh[k], 0.f);
        float* dst = &g_h3[(vox0 + j) * OC + obase];
        *(float4*)(dst)     = *(float4*)(o);
        *(float4*)(dst + 4) = *(float4*)(o + 4);
    }
}

// ---------------- Kernel 5: 1x1 head (64->4) + sigmoid ----------------
// warp per voxel; output layout [co][voxel] (== concat(pred[:,:3], pred[:,3:]))
__global__ __launch_bounds__(256) void k5_head(
    const float* __restrict__ w3c, const float* __restrict__ b3c,
    float* __restrict__ out)
{
    int warp = (blockIdx.x * blockDim.x + threadIdx.x) >> 5;
    int lane = threadIdx.x & 31;
    if (warp >= PP) return;
    const float* hrow = g_h3 + (size_t)warp * OC;
    float a0 = hrow[lane], a1 = hrow[lane + 32];

    float r0 = a0 * w3c[0 * OC + lane] + a1 * w3c[0 * OC + lane + 32];
    float r1 = a0 * w3c[1 * OC + lane] + a1 * w3c[1 * OC + lane + 32];
    float r2 = a0 * w3c[2 * OC + lane] + a1 * w3c[2 * OC + lane + 32];
    float r3 = a0 * w3c[3 * OC + lane] + a1 * w3c[3 * OC + lane + 32];
    #pragma unroll
    for (int off = 16; off; off >>= 1) {
        r0 += __shfl_xor_sync(0xffffffffu, r0, off);
        r1 += __shfl_xor_sync(0xffffffffu, r1, off);
        r2 += __shfl_xor_sync(0xffffffffu, r2, off);
        r3 += __shfl_xor_sync(0xffffffffu, r3, off);
    }
    if (lane == 0) {
        out[0 * PP + warp] = 1.f / (1.f + expf(-(r0 + b3c[0])));
        out[1 * PP + warp] = 1.f / (1.f + expf(-(r1 + b3c[1])));
        out[2 * PP + warp] = 1.f / (1.f + expf(-(r2 + b3c[2])));
        out[3 * PP + warp] = 1.f / (1.f + expf(-(r3 + b3c[3])));
    }
}

// ---------------- launch ----------------
extern "C" void kernel_launch(void* const* d_in, const int* in_sizes, int n_in,
                              void* d_out, int out_size)
{
    const float* img   = (const float*)d_in[0];
    const int*   xi    = (const int*)d_in[1];
    const int*   yi    = (const int*)d_in[2];
    const int*   valid = (const int*)d_in[3];   // bool -> int32 in harness
    const float* wproj = (const float*)d_in[4];
    const float* bproj = (const float*)d_in[5];
    const float* bn1g = (const float*)d_in[6];
    const float* bn1b = (const float*)d_in[7];
    const float* bn1m = (const float*)d_in[8];
    const float* bn1v = (const float*)d_in[9];
    const float* w3a  = (const float*)d_in[10];
    const float* b3a  = (const float*)d_in[11];
    const float* bn2g = (const float*)d_in[12];
    const float* bn2b = (const float*)d_in[13];
    const float* bn2m = (const float*)d_in[14];
    const float* bn2v = (const float*)d_in[15];
    const float* w3b  = (const float*)d_in[16];
    const float* b3b  = (const float*)d_in[17];
    const float* bn3g = (const float*)d_in[18];
    const float* bn3b = (const float*)d_in[19];
    const float* bn3m = (const float*)d_in[20];
    const float* bn3v = (const float*)d_in[21];
    const float* w3c  = (const float*)d_in[22];
    const float* b3c  = (const float*)d_in[23];
    float* out = (float*)d_out;

    k_wt<<<(OC * DM * 125 + 255) / 256, 256>>>(w3b);
    k1_proj<<<(NV * HWSZ) / 64, 128>>>(img, wproj, bproj, bn1g, bn1b, bn1m, bn1v);
    k2_fuse<<<PP, 128>>>(xi, yi, valid);
    k3_mix<<<PP / 64, 128>>>(w3a, b3a, bn2g, bn2b, bn2m, bn2v);
    k4_conv<<<dim3(VW / 16, VH / 16, VD), 256>>>(b3b, bn3g, bn3b, bn3m, bn3v);
    k5_head<<<(PP + 7) / 8, 256>>>(w3c, b3c, out);
}

// round 8
// speedup vs baseline: 2.5392x; 2.5392x over previous
#include <cuda_runtime.h>
#include <math.h>
#include <stdint.h>

#define NV 7
#define CIN 512
#define HH 64
#define WW 112
#define HWSZ (HH*WW)
#define DM 128
#define PP 36864
#define OC 64
#define BNEPS 1e-5f
// padded conv volume: 8 z-slices x 100 y x 100 x rows of 128ch, +512 guard rows each side
#define PR0 512
#define PROWS 81024

__device__ float g_feat[NV * HWSZ * DM];
__device__ float g_fused[PP * DM];
__device__ float g_h2p[(size_t)PROWS * 128];
__device__ float g_h3[PP * OC];
__device__ float g_wt[125 * OC * DM];   // [tap][o][c], tf32-rounded

__device__ __forceinline__ float to_tf32(float f) {
    uint32_t u; asm("cvt.rna.tf32.f32 %0, %1;" : "=r"(u) : "f"(f));
    return __uint_as_float(u);
}
__device__ __forceinline__ void mma8(float* d, const uint32_t* a, const uint32_t* b) {
    asm volatile(
        "mma.sync.aligned.m16n8k8.row.col.f32.tf32.tf32.f32 "
        "{%0,%1,%2,%3},{%4,%5,%6,%7},{%8,%9},{%0,%1,%2,%3};"
        : "+f"(d[0]), "+f"(d[1]), "+f"(d[2]), "+f"(d[3])
        : "r"(a[0]), "r"(a[1]), "r"(a[2]), "r"(a[3]), "r"(b[0]), "r"(b[1]));
}

// ---------- zero padded volume ----------
__global__ void k_zero() {
    size_t i = (size_t)blockIdx.x * 256 + threadIdx.x;
    if (i < (size_t)PROWS * 32) ((float4*)g_h2p)[i] = make_float4(0.f,0.f,0.f,0.f);
}
// ---------- weight prep: w3b[o][c][kd][kh][kw] -> g_wt[tap][o][c] (tf32) ----------
__global__ void k_wt(const float* __restrict__ w3b) {
    int idx = blockIdx.x * 256 + threadIdx.x;
    if (idx >= 125 * 8192) return;
    int t = idx >> 13, o = (idx >> 7) & 63, c = idx & 127;
    g_wt[idx] = to_tf32(w3b[(size_t)(o * 128 + c) * 125 + t]);
}

// ---------- k1: projection GEMM + BN1 + ReLU ----------
__global__ __launch_bounds__(128) void k1_proj(
    const float* __restrict__ img, const float* __restrict__ wproj, const float* __restrict__ bproj,
    const float* __restrict__ g1, const float* __restrict__ bb1,
    const float* __restrict__ m1, const float* __restrict__ v1)
{
    __shared__ __align__(16) float As[16][64];
    __shared__ __align__(16) float Bs[16][128];
    const int m0 = blockIdx.x * 64;
    const int n = m0 / HWSZ, hw0 = m0 % HWSZ;
    const int tid = threadIdx.x;
    const int r0 = (tid >> 4) * 8, c0 = (tid & 15) * 8;
    float acc[8][8];
    #pragma unroll
    for (int r = 0; r < 8; r++) {
        #pragma unroll
        for (int c = 0; c < 8; c++) acc[r][c] = 0.f;
    }
    const int li = tid & 63, jg = tid >> 6;
    for (int k0 = 0; k0 < CIN; k0 += 16) {
        __syncthreads();
        const float* Ab = img + ((size_t)n * CIN + k0 + jg * 8) * HWSZ + hw0 + li;
        #pragma unroll
        for (int jj = 0; jj < 8; jj++) As[jg * 8 + jj][li] = Ab[(size_t)jj * HWSZ];
        const float* Bb = wproj + (size_t)tid * CIN + k0;
        #pragma unroll
        for (int jj = 0; jj < 16; jj += 4) {
            float4 t = *(const float4*)(Bb + jj);
            Bs[jj][tid] = t.x; Bs[jj+1][tid] = t.y; Bs[jj+2][tid] = t.z; Bs[jj+3][tid] = t.w;
        }
        __syncthreads();
        #pragma unroll
        for (int j = 0; j < 16; j++) {
            float a[8], b[8];
            *(float4*)(a) = *(const float4*)&As[j][r0]; *(float4*)(a+4) = *(const float4*)&As[j][r0+4];
            *(float4*)(b) = *(const float4*)&Bs[j][c0]; *(float4*)(b+4) = *(const float4*)&Bs[j][c0+4];
            #pragma unroll
            for (int r = 0; r < 8; r++) {
                #pragma unroll
                for (int c = 0; c < 8; c++) acc[r][c] += a[r] * b[c];
            }
        }
    }
    float sc[8], sh[8];
    #pragma unroll
    for (int c = 0; c < 8; c++) {
        int d = c0 + c;
        float s = g1[d] * rsqrtf(v1[d] + BNEPS);
        sc[c] = s; sh[c] = (bproj[d] - m1[d]) * s + bb1[d];
    }
    #pragma unroll
    for (int r = 0; r < 8; r++) {
        float o[8];
        #pragma unroll
        for (int c = 0; c < 8; c++) o[c] = fmaxf(acc[r][c] * sc[c] + sh[c], 0.f);
        float* dst = &g_feat[(size_t)(m0 + r0 + r) * DM + c0];
        *(float4*)(dst) = *(float4*)(o); *(float4*)(dst + 4) = *(float4*)(o + 4);
    }
}

// ---------- k2: gather + masked softmax fusion ----------
__global__ __launch_bounds__(128) void k2_fuse(
    const int* __restrict__ xi, const int* __restrict__ yi, const int* __restrict__ valid)
{
    const int p = blockIdx.x, d = threadIdx.x;
    float vv[NV];
    #pragma unroll
    for (int n = 0; n < NV; n++) {
        float val = 0.f;
        if (valid[n * PP + p]) {
            int lin = yi[n * PP + p] * WW + xi[n * PP + p];
            val = g_feat[((size_t)(n * HWSZ + lin)) * DM + d];
        }
        vv[n] = val;
    }
    float mx = vv[0];
    #pragma unroll
    for (int n = 1; n < NV; n++) mx = fmaxf(mx, vv[n]);
    float s = 0.f, ws = 0.f;
    #pragma unroll
    for (int n = 0; n < NV; n++) { float e = expf(vv[n] - mx); s += e; ws += e * vv[n]; }
    g_fused[(size_t)p * DM + d] = ws / s;
}

// ---------- k3: 1x1 GEMM + BN2 + ReLU -> padded tf32 volume ----------
__global__ __launch_bounds__(128) void k3_mix(
    const float* __restrict__ w3a, const float* __restrict__ b3a,
    const float* __restrict__ g2, const float* __restrict__ bb2,
    const float* __restrict__ m2, const float* __restrict__ v2)
{
    __shared__ __align__(16) float As[16][64];
    __shared__ __align__(16) float Bs[16][128];
    const int m0 = blockIdx.x * 64;
    const int tid = threadIdx.x;
    const int r0 = (tid >> 4) * 8, c0 = (tid & 15) * 8;
    float acc[8][8];
    #pragma unroll
    for (int r = 0; r < 8; r++) {
        #pragma unroll
        for (int c = 0; c < 8; c++) acc[r][c] = 0.f;
    }
    const int mm = tid & 63, j0 = (tid >> 6) * 8;
    for (int k0 = 0; k0 < DM; k0 += 16) {
        __syncthreads();
        const float* Ab = g_fused + (size_t)(m0 + mm) * DM + k0 + j0;
        float4 t0 = *(const float4*)Ab, t1 = *(const float4*)(Ab + 4);
        As[j0][mm]=t0.x; As[j0+1][mm]=t0.y; As[j0+2][mm]=t0.z; As[j0+3][mm]=t0.w;
        As[j0+4][mm]=t1.x; As[j0+5][mm]=t1.y; As[j0+6][mm]=t1.z; As[j0+7][mm]=t1.w;
        const float* Bb = w3a + (size_t)tid * DM + k0;
        #pragma unroll
        for (int jj = 0; jj < 16; jj += 4) {
            float4 t = *(const float4*)(Bb + jj);
            Bs[jj][tid]=t.x; Bs[jj+1][tid]=t.y; Bs[jj+2][tid]=t.z; Bs[jj+3][tid]=t.w;
        }
        __syncthreads();
        #pragma unroll
        for (int j = 0; j < 16; j++) {
            float a[8], b[8];
            *(float4*)(a) = *(const float4*)&As[j][r0]; *(float4*)(a+4) = *(const float4*)&As[j][r0+4];
            *(float4*)(b) = *(const float4*)&Bs[j][c0]; *(float4*)(b+4) = *(const float4*)&Bs[j][c0+4];
            #pragma unroll
            for (int r = 0; r < 8; r++) {
                #pragma unroll
                for (int c = 0; c < 8; c++) acc[r][c] += a[r] * b[c];
            }
        }
    }
    float sc[8], sh[8];
    #pragma unroll
    for (int c = 0; c < 8; c++) {
        int d = c0 + c;
        float s = g2[d] * rsqrtf(v2[d] + BNEPS);
        sc[c] = s; sh[c] = (b3a[d] - m2[d]) * s + bb2[d];
    }
    #pragma unroll
    for (int r = 0; r < 8; r++) {
        int m = m0 + r0 + r;
        int z = m / 9216, rem = m % 9216, y = rem / 96, x = rem % 96;
        size_t pm = (size_t)(z + 2) * 10000 + (y + 2) * 100 + (x + 2) + PR0;
        float o[8];
        #pragma unroll
        for (int c = 0; c < 8; c++) o[c] = to_tf32(fmaxf(acc[r][c] * sc[c] + sh[c], 0.f));
        float* dst = g_h2p + pm * 128 + c0;
        *(float4*)(dst) = *(float4*)(o); *(float4*)(dst + 4) = *(float4*)(o + 4);
    }
}

// ---------- k4: 5x5x5 conv via mma.sync tf32 implicit GEMM ----------
// A staged once per (kd,kh), 132 rows; kw taps = row-offset views.
#define SA 132
#define SA_ROWS 132
#define SB_S 132
#define SMEM_K4 ((SA_ROWS*SA + 64*SB_S) * 4)   // 103488 bytes
__global__ __launch_bounds__(256, 2) void k4_mma(
    const float* __restrict__ b3b, const float* __restrict__ g3,
    const float* __restrict__ bb3, const float* __restrict__ m3, const float* __restrict__ v3)
{
    extern __shared__ __align__(16) float smem[];
    float* sA = smem;                       // [132][132]
    float* sB = smem + SA_ROWS * SA;        // [64][132]

    const int tid = threadIdx.x;
    const int lane = tid & 31, wid = tid >> 5;
    const int wm = wid >> 1, wn = wid & 1;  // 4 M-warps x 2 N-warps
    const int gq = lane >> 2, tq = lane & 3;
    const int m0 = 20000 + blockIdx.x * 128;

    float acc[2][4][4];
    #pragma unroll
    for (int mt = 0; mt < 2; mt++)
        #pragma unroll
        for (int nt = 0; nt < 4; nt++)
            #pragma unroll
            for (int q = 0; q < 4; q++) acc[mt][nt][q] = 0.f;

    for (int kd = 0; kd < 5; kd++) {
        for (int kh = 0; kh < 5; kh++) {
            const int arow0 = m0 + (kd - 2) * 10000 + (kh - 2) * 100 - 2;
            if (arow0 >= 60000 || arow0 + 131 < 20000) continue;  // all-zero slab
            __syncthreads();
            // stage A: 132 contiguous volume rows -> sA[row][c], stride 132
            {
                const float4* src = (const float4*)(g_h2p) + ((size_t)arow0 + PR0) * 32;
                #pragma unroll 4
                for (int i = tid; i < SA_ROWS * 32; i += 256) {
                    int r = i >> 5, c4 = i & 31;
                    *(float4*)(sA + r * SA + c4 * 4) = src[i];
                }
            }
            for (int kw = 0; kw < 5; kw++) {
                __syncthreads();   // prev compute done (B reuse) / A visible on first iter
                {
                    const int tap = (kd * 5 + kh) * 5 + kw;
                    const float4* src = (const float4*)(g_wt + (size_t)tap * 8192);
                    #pragma unroll 4
                    for (int i = tid; i < 64 * 32; i += 256) {
                        int r = i >> 5, c4 = i & 31;
                        *(float4*)(sB + r * SB_S + c4 * 4) = src[i];
                    }
                }
                __syncthreads();
                // 16 k-steps of m16n8k8
                #pragma unroll 4
                for (int ks = 0; ks < 16; ks++) {
                    const int k0 = ks * 8;
                    uint32_t a[2][4], b[4][2];
                    #pragma unroll
                    for (int mt = 0; mt < 2; mt++) {
                        const float* p = sA + (size_t)(wm * 32 + mt * 16 + gq + kw) * SA + k0 + tq;
                        a[mt][0] = __float_as_uint(p[0]);
                        a[mt][1] = __float_as_uint(p[8 * SA]);
                        a[mt][2] = __float_as_uint(p[4]);
                        a[mt][3] = __float_as_uint(p[8 * SA + 4]);
                    }
                    #pragma unroll
                    for (int nt = 0; nt < 4; nt++) {
                        const float* p = sB + (size_t)(wn * 32 + nt * 8 + gq) * SB_S + k0 + tq;
                        b[nt][0] = __float_as_uint(p[0]);
                        b[nt][1] = __float_as_uint(p[4]);
                    }
                    #pragma unroll
                    for (int mt = 0; mt < 2; mt++)
                        #pragma unroll
                        for (int nt = 0; nt < 4; nt++)
                            mma8(acc[mt][nt], a[mt], b[nt]);
                }
            }
        }
    }

    // epilogue: BN3 + ReLU, registers -> g_h3[vox][oc]
    float scv[4][2], shv[4][2];
    #pragma unroll
    for (int nt = 0; nt < 4; nt++) {
        #pragma unroll
        for (int j = 0; j < 2; j++) {
            int oc = wn * 32 + nt * 8 + 2 * tq + j;
            float s = g3[oc] * rsqrtf(v3[oc] + BNEPS);
            scv[nt][j] = s;
            shv[nt][j] = (b3b[oc] - m3[oc]) * s + bb3[oc];
        }
    }
    #pragma unroll
    for (int mt = 0; mt < 2; mt++) {
        #pragma unroll
        for (int h = 0; h < 2; h++) {
            int m = wm * 32 + mt * 16 + gq + h * 8;
            int pm = m0 + m;
            int zp = pm / 10000, r2 = pm % 10000, yp = r2 / 100, xp = r2 % 100;
            if (zp >= 2 && zp < 6 && yp >= 2 && yp < 98 && xp >= 2 && xp < 98) {
                int vox = (zp - 2) * 9216 + (yp - 2) * 96 + (xp - 2);
                float* dst = g_h3 + (size_t)vox * 64 + wn * 32 + 2 * tq;
                #pragma unroll
                for (int nt = 0; nt < 4; nt++) {
                    float2 v;
                    v.x = fmaxf(acc[mt][nt][h * 2 + 0] * scv[nt][0] + shv[nt][0], 0.f);
                    v.y = fmaxf(acc[mt][nt][h * 2 + 1] * scv[nt][1] + shv[nt][1], 0.f);
                    *(float2*)(dst + nt * 8) = v;
                }
            }
        }
    }
}

// ---------- k5: 1x1 head (64->4) + sigmoid ----------
__global__ __launch_bounds__(256) void k5_head(
    const float* __restrict__ w3c, const float* __restrict__ b3c, float* __restrict__ out)
{
    int warp = (blockIdx.x * blockDim.x + threadIdx.x) >> 5;
    int lane = threadIdx.x & 31;
    if (warp >= PP) return;
    const float* hrow = g_h3 + (size_t)warp * OC;
    float a0 = hrow[lane], a1 = hrow[lane + 32];
    float r0 = a0 * w3c[lane]        + a1 * w3c[lane + 32];
    float r1 = a0 * w3c[64 + lane]   + a1 * w3c[96 + lane];
    float r2 = a0 * w3c[128 + lane]  + a1 * w3c[160 + lane];
    float r3 = a0 * w3c[192 + lane]  + a1 * w3c[224 + lane];
    #pragma unroll
    for (int off = 16; off; off >>= 1) {
        r0 += __shfl_xor_sync(0xffffffffu, r0, off);
        r1 += __shfl_xor_sync(0xffffffffu, r1, off);
        r2 += __shfl_xor_sync(0xffffffffu, r2, off);
        r3 += __shfl_xor_sync(0xffffffffu, r3, off);
    }
    if (lane == 0) {
        out[0 * PP + warp] = 1.f / (1.f + expf(-(r0 + b3c[0])));
        out[1 * PP + warp] = 1.f / (1.f + expf(-(r1 + b3c[1])));
        out[2 * PP + warp] = 1.f / (1.f + expf(-(r2 + b3c[2])));
        out[3 * PP + warp] = 1.f / (1.f + expf(-(r3 + b3c[3])));
    }
}

extern "C" void kernel_launch(void* const* d_in, const int* in_sizes, int n_in,
                              void* d_out, int out_size)
{
    const float* img = (const float*)d_in[0];
    const int* xi = (const int*)d_in[1];
    const int* yi = (const int*)d_in[2];
    const int* valid = (const int*)d_in[3];
    const float* wproj = (const float*)d_in[4];
    const float* bproj = (const float*)d_in[5];
    const float* bn1g = (const float*)d_in[6];
    const float* bn1b = (const float*)d_in[7];
    const float* bn1m = (const float*)d_in[8];
    const float* bn1v = (const float*)d_in[9];
    const float* w3a = (const float*)d_in[10];
    const float* b3a = (const float*)d_in[11];
    const float* bn2g = (const float*)d_in[12];
    const float* bn2b = (const float*)d_in[13];
    const float* bn2m = (const float*)d_in[14];
    const float* bn2v = (const float*)d_in[15];
    const float* w3b = (const float*)d_in[16];
    const float* b3b = (const float*)d_in[17];
    const float* bn3g = (const float*)d_in[18];
    const float* bn3b = (const float*)d_in[19];
    const float* bn3m = (const float*)d_in[20];
    const float* bn3v = (const float*)d_in[21];
    const float* w3c = (const float*)d_in[22];
    const float* b3c = (const float*)d_in[23];
    float* out = (float*)d_out;

    cudaFuncSetAttribute(k4_mma, cudaFuncAttributeMaxDynamicSharedMemorySize, SMEM_K4);
    k_zero<<<(PROWS * 32 + 255) / 256, 256>>>();
    k_wt<<<(125 * 8192 + 255) / 256, 256>>>(w3b);
    k1_proj<<<(NV * HWSZ) / 64, 128>>>(img, wproj, bproj, bn1g, bn1b, bn1m, bn1v);
    k2_fuse<<<PP, 128>>>(xi, yi, valid);
    k3_mix<<<PP / 64, 128>>>(w3a, b3a, bn2g, bn2b, bn2m, bn2v);
    k4_mma<<<313, 256, SMEM_K4>>>(b3b, bn3g, bn3b, bn3m, bn3v);
    k5_head<<<(PP + 7) / 8, 256>>>(w3c, b3c, out);
}

// round 9
// speedup vs baseline: 2.8452x; 1.1205x over previous
#include <cuda_runtime.h>
#include <math.h>
#include <stdint.h>

#define NV 7
#define CIN 512
#define HH 64
#define WW 112
#define HWSZ (HH*WW)
#define DM 128
#define PP 36864
#define OC 64
#define BNEPS 1e-5f
#define PR0 512
#define PROWS 81024

__device__ float g_feat[NV * HWSZ * DM];
__device__ float g_fused[PP * DM];
__device__ float g_h2p[(size_t)PROWS * 128];
__device__ float g_h3[PP * OC];
__device__ float g_wt[125 * OC * DM];   // [tap][o][c], tf32-rounded

__device__ __forceinline__ float to_tf32(float f) {
    uint32_t u; asm("cvt.rna.tf32.f32 %0, %1;" : "=r"(u) : "f"(f));
    return __uint_as_float(u);
}
__device__ __forceinline__ void mma8(float* d, const uint32_t* a, const uint32_t* b) {
    asm volatile(
        "mma.sync.aligned.m16n8k8.row.col.f32.tf32.tf32.f32 "
        "{%0,%1,%2,%3},{%4,%5,%6,%7},{%8,%9},{%0,%1,%2,%3};"
        : "+f"(d[0]), "+f"(d[1]), "+f"(d[2]), "+f"(d[3])
        : "r"(a[0]), "r"(a[1]), "r"(a[2]), "r"(a[3]), "r"(b[0]), "r"(b[1]));
}

// ---------- zero padded volume ----------
__global__ void k_zero() {
    size_t i = (size_t)blockIdx.x * 256 + threadIdx.x;
    if (i < (size_t)PROWS * 32) ((float4*)g_h2p)[i] = make_float4(0.f,0.f,0.f,0.f);
}
// ---------- weight prep: w3b[o][c][kd][kh][kw] -> g_wt[tap][o][c] (tf32) ----------
__global__ void k_wt(const float* __restrict__ w3b) {
    int idx = blockIdx.x * 256 + threadIdx.x;
    if (idx >= 125 * 8192) return;
    int t = idx >> 13, o = (idx >> 7) & 63, c = idx & 127;
    g_wt[idx] = to_tf32(w3b[(size_t)(o * 128 + c) * 125 + t]);
}

// ---------- k1: projection GEMM via mma.sync + BN1 + ReLU ----------
// C[m][d] = sum_k img[n][k][hw]*wproj[d][k];  M-tile 128, N=128, BK=32.
__global__ __launch_bounds__(256) void k1_mma(
    const float* __restrict__ img, const float* __restrict__ wproj, const float* __restrict__ bproj,
    const float* __restrict__ g1, const float* __restrict__ bb1,
    const float* __restrict__ m1, const float* __restrict__ v1)
{
    __shared__ float sA[32][136];   // [k][m], stride 136 (=8 mod 32): all paths conflict-free
    __shared__ float sB[128][36];   // [d][k], stride 36 (=4 mod 32)
    const int tid = threadIdx.x;
    const int lane = tid & 31, wid = tid >> 5;
    const int gq = lane >> 2, tq = lane & 3;
    const int wm = wid >> 1, wn = wid & 1;      // 4 M-warps x 2 N-warps(64 cols)
    const int m0 = blockIdx.x * 128;
    const int n = m0 / HWSZ, hw0 = m0 % HWSZ;   // 7168%128==0

    float acc[2][8][4];
    #pragma unroll
    for (int mt = 0; mt < 2; mt++)
        #pragma unroll
        for (int nt = 0; nt < 8; nt++)
            #pragma unroll
            for (int q = 0; q < 4; q++) acc[mt][nt][q] = 0.f;

    for (int k0 = 0; k0 < CIN; k0 += 32) {
        __syncthreads();
        // A: img k-major -> sA[kk][mm]; coalesced along m
        const float* asrc = img + ((size_t)n * CIN + k0) * HWSZ + hw0;
        #pragma unroll 4
        for (int i = tid; i < 4096; i += 256) {
            int kk = i >> 7, mm = i & 127;
            sA[kk][mm] = to_tf32(asrc[(size_t)kk * HWSZ + mm]);
        }
        // B: wproj[d][k] -> sB[d][kk]; coalesced along k
        #pragma unroll 4
        for (int i = tid; i < 4096; i += 256) {
            int d = i >> 5, kk = i & 31;
            sB[d][kk] = to_tf32(wproj[(size_t)d * CIN + k0 + kk]);
        }
        __syncthreads();
        #pragma unroll
        for (int ks = 0; ks < 4; ks++) {
            const int k = ks * 8;
            uint32_t a[2][4], b[8][2];
            #pragma unroll
            for (int mt = 0; mt < 2; mt++) {
                int row = wm * 32 + mt * 16 + gq;
                a[mt][0] = __float_as_uint(sA[k + tq][row]);
                a[mt][1] = __float_as_uint(sA[k + tq][row + 8]);
                a[mt][2] = __float_as_uint(sA[k + tq + 4][row]);
                a[mt][3] = __float_as_uint(sA[k + tq + 4][row + 8]);
            }
            #pragma unroll
            for (int nt = 0; nt < 8; nt++) {
                int dc = wn * 64 + nt * 8 + gq;
                b[nt][0] = __float_as_uint(sB[dc][k + tq]);
                b[nt][1] = __float_as_uint(sB[dc][k + tq + 4]);
            }
            #pragma unroll
            for (int mt = 0; mt < 2; mt++)
                #pragma unroll
                for (int nt = 0; nt < 8; nt++)
                    mma8(acc[mt][nt], a[mt], b[nt]);
        }
    }
    // epilogue: bias + BN1 + ReLU
    float scv[8][2], shv[8][2];
    #pragma unroll
    for (int nt = 0; nt < 8; nt++) {
        #pragma unroll
        for (int j = 0; j < 2; j++) {
            int d = wn * 64 + nt * 8 + 2 * tq + j;
            float s = g1[d] * rsqrtf(v1[d] + BNEPS);
            scv[nt][j] = s;
            shv[nt][j] = (bproj[d] - m1[d]) * s + bb1[d];
        }
    }
    #pragma unroll
    for (int mt = 0; mt < 2; mt++) {
        #pragma unroll
        for (int h = 0; h < 2; h++) {
            int m = m0 + wm * 32 + mt * 16 + gq + h * 8;
            float* dst = g_feat + (size_t)m * DM + wn * 64 + 2 * tq;
            #pragma unroll
            for (int nt = 0; nt < 8; nt++) {
                float2 v;
                v.x = fmaxf(acc[mt][nt][h * 2 + 0] * scv[nt][0] + shv[nt][0], 0.f);
                v.y = fmaxf(acc[mt][nt][h * 2 + 1] * scv[nt][1] + shv[nt][1], 0.f);
                *(float2*)(dst + nt * 8) = v;
            }
        }
    }
}

// ---------- k2: gather + masked softmax fusion ----------
__global__ __launch_bounds__(128) void k2_fuse(
    const int* __restrict__ xi, const int* __restrict__ yi, const int* __restrict__ valid)
{
    const int p = blockIdx.x, d = threadIdx.x;
    float vv[NV];
    #pragma unroll
    for (int n = 0; n < NV; n++) {
        float val = 0.f;
        if (valid[n * PP + p]) {
            int lin = yi[n * PP + p] * WW + xi[n * PP + p];
            val = g_feat[((size_t)(n * HWSZ + lin)) * DM + d];
        }
        vv[n] = val;
    }
    float mx = vv[0];
    #pragma unroll
    for (int n = 1; n < NV; n++) mx = fmaxf(mx, vv[n]);
    float s = 0.f, ws = 0.f;
    #pragma unroll
    for (int n = 0; n < NV; n++) { float e = expf(vv[n] - mx); s += e; ws += e * vv[n]; }
    g_fused[(size_t)p * DM + d] = ws / s;
}

// ---------- k3: 1x1 GEMM via mma.sync + BN2 + ReLU -> padded tf32 volume ----------
__global__ __launch_bounds__(256) void k3_mma(
    const float* __restrict__ w3a, const float* __restrict__ b3a,
    const float* __restrict__ g2, const float* __restrict__ bb2,
    const float* __restrict__ m2, const float* __restrict__ v2)
{
    __shared__ float sA[128][36];   // [m][k]
    __shared__ float sB[128][36];   // [d][k]
    const int tid = threadIdx.x;
    const int lane = tid & 31, wid = tid >> 5;
    const int gq = lane >> 2, tq = lane & 3;
    const int wm = wid >> 1, wn = wid & 1;
    const int m0 = blockIdx.x * 128;

    float acc[2][8][4];
    #pragma unroll
    for (int mt = 0; mt < 2; mt++)
        #pragma unroll
        for (int nt = 0; nt < 8; nt++)
            #pragma unroll
            for (int q = 0; q < 4; q++) acc[mt][nt][q] = 0.f;

    for (int k0 = 0; k0 < DM; k0 += 32) {
        __syncthreads();
        #pragma unroll 4
        for (int i = tid; i < 4096; i += 256) {
            int mm = i >> 5, kk = i & 31;
            sA[mm][kk] = to_tf32(g_fused[(size_t)(m0 + mm) * DM + k0 + kk]);
            sB[mm][kk] = to_tf32(w3a[(size_t)mm * DM + k0 + kk]);
        }
        __syncthreads();
        #pragma unroll
        for (int ks = 0; ks < 4; ks++) {
            const int k = ks * 8;
            uint32_t a[2][4], b[8][2];
            #pragma unroll
            for (int mt = 0; mt < 2; mt++) {
                const float* p = &sA[wm * 32 + mt * 16 + gq][k + tq];
                a[mt][0] = __float_as_uint(p[0]);
                a[mt][1] = __float_as_uint(p[8 * 36]);
                a[mt][2] = __float_as_uint(p[4]);
                a[mt][3] = __float_as_uint(p[8 * 36 + 4]);
            }
            #pragma unroll
            for (int nt = 0; nt < 8; nt++) {
                const float* p = &sB[wn * 64 + nt * 8 + gq][k + tq];
                b[nt][0] = __float_as_uint(p[0]);
                b[nt][1] = __float_as_uint(p[4]);
            }
            #pragma unroll
            for (int mt = 0; mt < 2; mt++)
                #pragma unroll
                for (int nt = 0; nt < 8; nt++)
                    mma8(acc[mt][nt], a[mt], b[nt]);
        }
    }
    float scv[8][2], shv[8][2];
    #pragma unroll
    for (int nt = 0; nt < 8; nt++) {
        #pragma unroll
        for (int j = 0; j < 2; j++) {
            int d = wn * 64 + nt * 8 + 2 * tq + j;
            float s = g2[d] * rsqrtf(v2[d] + BNEPS);
            scv[nt][j] = s;
            shv[nt][j] = (b3a[d] - m2[d]) * s + bb2[d];
        }
    }
    #pragma unroll
    for (int mt = 0; mt < 2; mt++) {
        #pragma unroll
        for (int h = 0; h < 2; h++) {
            int m = m0 + wm * 32 + mt * 16 + gq + h * 8;
            int z = m / 9216, rem = m % 9216, y = rem / 96, x = rem % 96;
            size_t pm = (size_t)(z + 2) * 10000 + (y + 2) * 100 + (x + 2) + PR0;
            float* dst = g_h2p + pm * 128 + wn * 64 + 2 * tq;
            #pragma unroll
            for (int nt = 0; nt < 8; nt++) {
                float2 v;
                v.x = to_tf32(fmaxf(acc[mt][nt][h * 2 + 0] * scv[nt][0] + shv[nt][0], 0.f));
                v.y = to_tf32(fmaxf(acc[mt][nt][h * 2 + 1] * scv[nt][1] + shv[nt][1], 0.f));
                *(float2*)(dst + nt * 8) = v;
            }
        }
    }
}

// ---------- k4: 5x5x5 conv via mma.sync tf32 implicit GEMM (unchanged) ----------
#define SA 132
#define SA_ROWS 132
#define SB_S 132
#define SMEM_K4 ((SA_ROWS*SA + 64*SB_S) * 4)
__global__ __launch_bounds__(256, 2) void k4_mma(
    const float* __restrict__ b3b, const float* __restrict__ g3,
    const float* __restrict__ bb3, const float* __restrict__ m3, const float* __restrict__ v3)
{
    extern __shared__ __align__(16) float smem[];
    float* sA = smem;
    float* sB = smem + SA_ROWS * SA;

    const int tid = threadIdx.x;
    const int lane = tid & 31, wid = tid >> 5;
    const int wm = wid >> 1, wn = wid & 1;
    const int gq = lane >> 2, tq = lane & 3;
    const int m0 = 20000 + blockIdx.x * 128;

    float acc[2][4][4];
    #pragma unroll
    for (int mt = 0; mt < 2; mt++)
        #pragma unroll
        for (int nt = 0; nt < 4; nt++)
            #pragma unroll
            for (int q = 0; q < 4; q++) acc[mt][nt][q] = 0.f;

    for (int kd = 0; kd < 5; kd++) {
        for (int kh = 0; kh < 5; kh++) {
            const int arow0 = m0 + (kd - 2) * 10000 + (kh - 2) * 100 - 2;
            if (arow0 >= 60000 || arow0 + 131 < 20000) continue;
            __syncthreads();
            {
                const float4* src = (const float4*)(g_h2p) + ((size_t)arow0 + PR0) * 32;
                #pragma unroll 4
                for (int i = tid; i < SA_ROWS * 32; i += 256) {
                    int r = i >> 5, c4 = i & 31;
                    *(float4*)(sA + r * SA + c4 * 4) = src[i];
                }
            }
            for (int kw = 0; kw < 5; kw++) {
                __syncthreads();
                {
                    const int tap = (kd * 5 + kh) * 5 + kw;
                    const float4* src = (const float4*)(g_wt + (size_t)tap * 8192);
                    #pragma unroll 4
                    for (int i = tid; i < 64 * 32; i += 256) {
                        int r = i >> 5, c4 = i & 31;
                        *(float4*)(sB + r * SB_S + c4 * 4) = src[i];
                    }
                }
                __syncthreads();
                #pragma unroll 4
                for (int ks = 0; ks < 16; ks++) {
                    const int k0 = ks * 8;
                    uint32_t a[2][4], b[4][2];
                    #pragma unroll
                    for (int mt = 0; mt < 2; mt++) {
                        const float* p = sA + (size_t)(wm * 32 + mt * 16 + gq + kw) * SA + k0 + tq;
                        a[mt][0] = __float_as_uint(p[0]);
                        a[mt][1] = __float_as_uint(p[8 * SA]);
                        a[mt][2] = __float_as_uint(p[4]);
                        a[mt][3] = __float_as_uint(p[8 * SA + 4]);
                    }
                    #pragma unroll
                    for (int nt = 0; nt < 4; nt++) {
                        const float* p = sB + (size_t)(wn * 32 + nt * 8 + gq) * SB_S + k0 + tq;
                        b[nt][0] = __float_as_uint(p[0]);
                        b[nt][1] = __float_as_uint(p[4]);
                    }
                    #pragma unroll
                    for (int mt = 0; mt < 2; mt++)
                        #pragma unroll
                        for (int nt = 0; nt < 4; nt++)
                            mma8(acc[mt][nt], a[mt], b[nt]);
                }
            }
        }
    }

    float scv[4][2], shv[4][2];
    #pragma unroll
    for (int nt = 0; nt < 4; nt++) {
        #pragma unroll
        for (int j = 0; j < 2; j++) {
            int oc = wn * 32 + nt * 8 + 2 * tq + j;
            float s = g3[oc] * rsqrtf(v3[oc] + BNEPS);
            scv[nt][j] = s;
            shv[nt][j] = (b3b[oc] - m3[oc]) * s + bb3[oc];
        }
    }
    #pragma unroll
    for (int mt = 0; mt < 2; mt++) {
        #pragma unroll
        for (int h = 0; h < 2; h++) {
            int m = wm * 32 + mt * 16 + gq + h * 8;
            int pm = m0 + m;
            int zp = pm / 10000, r2 = pm % 10000, yp = r2 / 100, xp = r2 % 100;
            if (zp >= 2 && zp < 6 && yp >= 2 && yp < 98 && xp >= 2 && xp < 98) {
                int vox = (zp - 2) * 9216 + (yp - 2) * 96 + (xp - 2);
                float* dst = g_h3 + (size_t)vox * 64 + wn * 32 + 2 * tq;
                #pragma unroll
                for (int nt = 0; nt < 4; nt++) {
                    float2 v;
                    v.x = fmaxf(acc[mt][nt][h * 2 + 0] * scv[nt][0] + shv[nt][0], 0.f);
                    v.y = fmaxf(acc[mt][nt][h * 2 + 1] * scv[nt][1] + shv[nt][1], 0.f);
                    *(float2*)(dst + nt * 8) = v;
                }
            }
        }
    }
}

// ---------- k5: 1x1 head (64->4) + sigmoid, thread-per-voxel ----------
__global__ __launch_bounds__(256) void k5_head(
    const float* __restrict__ w3c, const float* __restrict__ b3c, float* __restrict__ out)
{
    __shared__ float sw[256];
    const int tid = threadIdx.x;
    sw[tid] = w3c[tid];
    __syncthreads();
    const int vox = blockIdx.x * 256 + tid;
    const float4* h = (const float4*)(g_h3 + (size_t)vox * OC);
    float r0 = b3c[0], r1 = b3c[1], r2 = b3c[2], r3 = b3c[3];
    #pragma unroll
    for (int q = 0; q < 16; q++) {
        float4 v = h[q];
        const float* w0 = sw + q * 4;
        r0 += v.x * w0[0]       + v.y * w0[1]       + v.z * w0[2]       + v.w * w0[3];
        r1 += v.x * w0[64]      + v.y * w0[65]      + v.z * w0[66]      + v.w * w0[67];
        r2 += v.x * w0[128]     + v.y * w0[129]     + v.z * w0[130]     + v.w * w0[131];
        r3 += v.x * w0[192]     + v.y * w0[193]     + v.z * w0[194]     + v.w * w0[195];
    }
    out[0 * PP + vox] = 1.f / (1.f + expf(-r0));
    out[1 * PP + vox] = 1.f / (1.f + expf(-r1));
    out[2 * PP + vox] = 1.f / (1.f + expf(-r2));
    out[3 * PP + vox] = 1.f / (1.f + expf(-r3));
}

extern "C" void kernel_launch(void* const* d_in, const int* in_sizes, int n_in,
                              void* d_out, int out_size)
{
    const float* img = (const float*)d_in[0];
    const int* xi = (const int*)d_in[1];
    const int* yi = (const int*)d_in[2];
    const int* valid = (const int*)d_in[3];
    const float* wproj = (const float*)d_in[4];
    const float* bproj = (const float*)d_in[5];
    const float* bn1g = (const float*)d_in[6];
    const float* bn1b = (const float*)d_in[7];
    const float* bn1m = (const float*)d_in[8];
    const float* bn1v = (const float*)d_in[9];
    const float* w3a = (const float*)d_in[10];
    const float* b3a = (const float*)d_in[11];
    const float* bn2g = (const float*)d_in[12];
    const float* bn2b = (const float*)d_in[13];
    const float* bn2m = (const float*)d_in[14];
    const float* bn2v = (const float*)d_in[15];
    const float* w3b = (const float*)d_in[16];
    const float* b3b = (const float*)d_in[17];
    const float* bn3g = (const float*)d_in[18];
    const float* bn3b = (const float*)d_in[19];
    const float* bn3m = (const float*)d_in[20];
    const float* bn3v = (const float*)d_in[21];
    const float* w3c = (const float*)d_in[22];
    const float* b3c = (const float*)d_in[23];
    float* out = (float*)d_out;

    cudaFuncSetAttribute(k4_mma, cudaFuncAttributeMaxDynamicSharedMemorySize, SMEM_K4);
    k_zero<<<(PROWS * 32 + 255) / 256, 256>>>();
    k_wt<<<(125 * 8192 + 255) / 256, 256>>>(w3b);
    k1_mma<<<(NV * HWSZ) / 128, 256>>>(img, wproj, bproj, bn1g, bn1b, bn1m, bn1v);
    k2_fuse<<<PP, 128>>>(xi, yi, valid);
    k3_mma<<<PP / 128, 256>>>(w3a, b3a, bn2g, bn2b, bn2m, bn2v);
    k4_mma<<<313, 256, SMEM_K4>>>(b3b, bn3g, bn3b, bn3m, bn3v);
    k5_head<<<PP / 256, 256>>>(w3c, b3c, out);
}

// round 11
// speedup vs baseline: 4.3324x; 1.5227x over previous
#include <cuda_runtime.h>
#include <cuda_bf16.h>
#include <math.h>
#include <stdint.h>

#define NV 7
#define CIN 512
#define HH 64
#define WW 112
#define HWSZ (HH*WW)
#define DM 128
#define PP 36864
#define OC 64
#define BNEPS 1e-5f
#define PR0 512
#define PROWS 81024

__device__ float g_feat[NV * HWSZ * DM];
__device__ float g_fused[PP * DM];
__device__ __nv_bfloat16 g_h2p[(size_t)PROWS * 128];
__device__ float g_h3[PP * OC];
__device__ __nv_bfloat16 g_wt[125 * OC * DM];   // [tap][o][c], bf16

__device__ __forceinline__ float to_tf32(float f) {
    uint32_t u; asm("cvt.rna.tf32.f32 %0, %1;" : "=r"(u) : "f"(f));
    return __uint_as_float(u);
}
__device__ __forceinline__ void mma8(float* d, const uint32_t* a, const uint32_t* b) {
    asm volatile(
        "mma.sync.aligned.m16n8k8.row.col.f32.tf32.tf32.f32 "
        "{%0,%1,%2,%3},{%4,%5,%6,%7},{%8,%9},{%0,%1,%2,%3};"
        : "+f"(d[0]), "+f"(d[1]), "+f"(d[2]), "+f"(d[3])
        : "r"(a[0]), "r"(a[1]), "r"(a[2]), "r"(a[3]), "r"(b[0]), "r"(b[1]));
}
__device__ __forceinline__ void mma16(float* d, const uint32_t* a, const uint32_t* b) {
    asm volatile(
        "mma.sync.aligned.m16n8k16.row.col.f32.bf16.bf16.f32 "
        "{%0,%1,%2,%3},{%4,%5,%6,%7},{%8,%9},{%0,%1,%2,%3};"
        : "+f"(d[0]), "+f"(d[1]), "+f"(d[2]), "+f"(d[3])
        : "r"(a[0]), "r"(a[1]), "r"(a[2]), "r"(a[3]), "r"(b[0]), "r"(b[1]));
}

// ---------- zero padded volume (bf16) ----------
__global__ void k_zero() {
    size_t i = (size_t)blockIdx.x * 256 + threadIdx.x;
    if (i < (size_t)PROWS * 16)
        ((uint4*)g_h2p)[i] = make_uint4(0u, 0u, 0u, 0u);
}
// ---------- weight prep: w3b[o][c][kd][kh][kw] -> g_wt[tap][o][c] (bf16) ----------
__global__ void k_wt(const float* __restrict__ w3b) {
    int idx = blockIdx.x * 256 + threadIdx.x;
    if (idx >= 125 * 8192) return;
    int t = idx >> 13, o = (idx >> 7) & 63, c = idx & 127;
    g_wt[idx] = __float2bfloat16_rn(w3b[(size_t)(o * 128 + c) * 125 + t]);
}

// ---------- k1: projection GEMM via mma.sync tf32 + BN1 + ReLU ----------
__global__ __launch_bounds__(256) void k1_mma(
    const float* __restrict__ img, const float* __restrict__ wproj, const float* __restrict__ bproj,
    const float* __restrict__ g1, const float* __restrict__ bb1,
    const float* __restrict__ m1, const float* __restrict__ v1)
{
    __shared__ float sA[32][136];
    __shared__ float sB[128][36];
    const int tid = threadIdx.x;
    const int lane = tid & 31, wid = tid >> 5;
    const int gq = lane >> 2, tq = lane & 3;
    const int wm = wid >> 1, wn = wid & 1;
    const int m0 = blockIdx.x * 128;
    const int n = m0 / HWSZ, hw0 = m0 % HWSZ;

    float acc[2][8][4];
    #pragma unroll
    for (int mt = 0; mt < 2; mt++)
        #pragma unroll
        for (int nt = 0; nt < 8; nt++)
            #pragma unroll
            for (int q = 0; q < 4; q++) acc[mt][nt][q] = 0.f;

    for (int k0 = 0; k0 < CIN; k0 += 32) {
        __syncthreads();
        const float* asrc = img + ((size_t)n * CIN + k0) * HWSZ + hw0;
        #pragma unroll 4
        for (int i = tid; i < 4096; i += 256) {
            int kk = i >> 7, mm = i & 127;
            sA[kk][mm] = to_tf32(asrc[(size_t)kk * HWSZ + mm]);
        }
        #pragma unroll 4
        for (int i = tid; i < 4096; i += 256) {
            int d = i >> 5, kk = i & 31;
            sB[d][kk] = to_tf32(wproj[(size_t)d * CIN + k0 + kk]);
        }
        __syncthreads();
        #pragma unroll
        for (int ks = 0; ks < 4; ks++) {
            const int k = ks * 8;
            uint32_t a[2][4], b[8][2];
            #pragma unroll
            for (int mt = 0; mt < 2; mt++) {
                int row = wm * 32 + mt * 16 + gq;
                a[mt][0] = __float_as_uint(sA[k + tq][row]);
                a[mt][1] = __float_as_uint(sA[k + tq][row + 8]);
                a[mt][2] = __float_as_uint(sA[k + tq + 4][row]);
                a[mt][3] = __float_as_uint(sA[k + tq + 4][row + 8]);
            }
            #pragma unroll
            for (int nt = 0; nt < 8; nt++) {
                int dc = wn * 64 + nt * 8 + gq;
                b[nt][0] = __float_as_uint(sB[dc][k + tq]);
                b[nt][1] = __float_as_uint(sB[dc][k + tq + 4]);
            }
            #pragma unroll
            for (int mt = 0; mt < 2; mt++)
                #pragma unroll
                for (int nt = 0; nt < 8; nt++)
                    mma8(acc[mt][nt], a[mt], b[nt]);
        }
    }
    float scv[8][2], shv[8][2];
    #pragma unroll
    for (int nt = 0; nt < 8; nt++) {
        #pragma unroll
        for (int j = 0; j < 2; j++) {
            int d = wn * 64 + nt * 8 + 2 * tq + j;
            float s = g1[d] * rsqrtf(v1[d] + BNEPS);
            scv[nt][j] = s;
            shv[nt][j] = (bproj[d] - m1[d]) * s + bb1[d];
        }
    }
    #pragma unroll
    for (int mt = 0; mt < 2; mt++) {
        #pragma unroll
        for (int h = 0; h < 2; h++) {
            int m = m0 + wm * 32 + mt * 16 + gq + h * 8;
            float* dst = g_feat + (size_t)m * DM + wn * 64 + 2 * tq;
            #pragma unroll
            for (int nt = 0; nt < 8; nt++) {
                float2 v;
                v.x = fmaxf(acc[mt][nt][h * 2 + 0] * scv[nt][0] + shv[nt][0], 0.f);
                v.y = fmaxf(acc[mt][nt][h * 2 + 1] * scv[nt][1] + shv[nt][1], 0.f);
                *(float2*)(dst + nt * 8) = v;
            }
        }
    }
}

// ---------- k2: gather + masked softmax fusion ----------
__global__ __launch_bounds__(128) void k2_fuse(
    const int* __restrict__ xi, const int* __restrict__ yi, const int* __restrict__ valid)
{
    const int p = blockIdx.x, d = threadIdx.x;
    float vv[NV];
    #pragma unroll
    for (int n = 0; n < NV; n++) {
        float val = 0.f;
        if (valid[n * PP + p]) {
            int lin = yi[n * PP + p] * WW + xi[n * PP + p];
            val = g_feat[((size_t)(n * HWSZ + lin)) * DM + d];
        }
        vv[n] = val;
    }
    float mx = vv[0];
    #pragma unroll
    for (int n = 1; n < NV; n++) mx = fmaxf(mx, vv[n]);
    float s = 0.f, ws = 0.f;
    #pragma unroll
    for (int n = 0; n < NV; n++) { float e = expf(vv[n] - mx); s += e; ws += e * vv[n]; }
    g_fused[(size_t)p * DM + d] = ws / s;
}

// ---------- k3: 1x1 GEMM via mma.sync tf32 + BN2 + ReLU -> padded bf16 volume ----------
__global__ __launch_bounds__(256) void k3_mma(
    const float* __restrict__ w3a, const float* __restrict__ b3a,
    const float* __restrict__ g2, const float* __restrict__ bb2,
    const float* __restrict__ m2, const float* __restrict__ v2)
{
    __shared__ float sA[128][36];
    __shared__ float sB[128][36];
    const int tid = threadIdx.x;
    const int lane = tid & 31, wid = tid >> 5;
    const int gq = lane >> 2, tq = lane & 3;
    const int wm = wid >> 1, wn = wid & 1;
    const int m0 = blockIdx.x * 128;

    float acc[2][8][4];
    #pragma unroll
    for (int mt = 0; mt < 2; mt++)
        #pragma unroll
        for (int nt = 0; nt < 8; nt++)
            #pragma unroll
            for (int q = 0; q < 4; q++) acc[mt][nt][q] = 0.f;

    for (int k0 = 0; k0 < DM; k0 += 32) {
        __syncthreads();
        #pragma unroll 4
        for (int i = tid; i < 4096; i += 256) {
            int mm = i >> 5, kk = i & 31;
            sA[mm][kk] = to_tf32(g_fused[(size_t)(m0 + mm) * DM + k0 + kk]);
            sB[mm][kk] = to_tf32(w3a[(size_t)mm * DM + k0 + kk]);
        }
        __syncthreads();
        #pragma unroll
        for (int ks = 0; ks < 4; ks++) {
            const int k = ks * 8;
            uint32_t a[2][4], b[8][2];
            #pragma unroll
            for (int mt = 0; mt < 2; mt++) {
                const float* p = &sA[wm * 32 + mt * 16 + gq][k + tq];
                a[mt][0] = __float_as_uint(p[0]);
                a[mt][1] = __float_as_uint(p[8 * 36]);
                a[mt][2] = __float_as_uint(p[4]);
                a[mt][3] = __float_as_uint(p[8 * 36 + 4]);
            }
            #pragma unroll
            for (int nt = 0; nt < 8; nt++) {
                const float* p = &sB[wn * 64 + nt * 8 + gq][k + tq];
                b[nt][0] = __float_as_uint(p[0]);
                b[nt][1] = __float_as_uint(p[4]);
            }
            #pragma unroll
            for (int mt = 0; mt < 2; mt++)
                #pragma unroll
                for (int nt = 0; nt < 8; nt++)
                    mma8(acc[mt][nt], a[mt], b[nt]);
        }
    }
    float scv[8][2], shv[8][2];
    #pragma unroll
    for (int nt = 0; nt < 8; nt++) {
        #pragma unroll
        for (int j = 0; j < 2; j++) {
            int d = wn * 64 + nt * 8 + 2 * tq + j;
            float s = g2[d] * rsqrtf(v2[d] + BNEPS);
            scv[nt][j] = s;
            shv[nt][j] = (b3a[d] - m2[d]) * s + bb2[d];
        }
    }
    #pragma unroll
    for (int mt = 0; mt < 2; mt++) {
        #pragma unroll
        for (int h = 0; h < 2; h++) {
            int m = m0 + wm * 32 + mt * 16 + gq + h * 8;
            int z = m / 9216, rem = m % 9216, y = rem / 96, x = rem % 96;
            size_t pm = (size_t)(z + 2) * 10000 + (y + 2) * 100 + (x + 2) + PR0;
            __nv_bfloat16* dst = g_h2p + pm * 128 + wn * 64 + 2 * tq;
            #pragma unroll
            for (int nt = 0; nt < 8; nt++) {
                float vx = fmaxf(acc[mt][nt][h * 2 + 0] * scv[nt][0] + shv[nt][0], 0.f);
                float vy = fmaxf(acc[mt][nt][h * 2 + 1] * scv[nt][1] + shv[nt][1], 0.f);
                *(__nv_bfloat162*)(dst + nt * 8) = __floats2bfloat162_rn(vx, vy);
            }
        }
    }
}

// ---------- k4: 5x5x5 conv via mma.sync bf16 implicit GEMM ----------
// 8 warps (4M x 2N), warp = m32 x n32. A staged per (kd,kh); B per kw.
// Strides 136 bf16 (=272B, 16B-aligned; word-stride mod 32 = 4 -> conflict-free frags)
#define SA_ST 136
#define SB_ST 136
#define SA_BYTES (132 * SA_ST * 2)      // 35904
#define SB_BYTES (64 * SB_ST * 2)       // 17408
#define SMEM_K4 (SA_BYTES + SB_BYTES)   // 53312
__global__ __launch_bounds__(256, 3) void k4_mma(
    const float* __restrict__ b3b, const float* __restrict__ g3,
    const float* __restrict__ bb3, const float* __restrict__ m3, const float* __restrict__ v3)
{
    extern __shared__ __align__(16) char smem[];
    __nv_bfloat16* sA = (__nv_bfloat16*)smem;                 // [132][136]
    __nv_bfloat16* sB = (__nv_bfloat16*)(smem + SA_BYTES);    // [64][136]

    const int tid = threadIdx.x;
    const int lane = tid & 31, wid = tid >> 5;
    const int wm = wid >> 1, wn = wid & 1;
    const int gq = lane >> 2, tq = lane & 3;
    const int m0 = 20000 + blockIdx.x * 128;

    float acc[2][4][4];
    #pragma unroll
    for (int mt = 0; mt < 2; mt++)
        #pragma unroll
        for (int nt = 0; nt < 4; nt++)
            #pragma unroll
            for (int q = 0; q < 4; q++) acc[mt][nt][q] = 0.f;

    for (int kd = 0; kd < 5; kd++) {
        for (int kh = 0; kh < 5; kh++) {
            const int arow0 = m0 + (kd - 2) * 10000 + (kh - 2) * 100 - 2;
            if (arow0 >= 60000 || arow0 + 131 < 20000) continue;  // all-zero slab
            __syncthreads();
            // stage A: 132 rows x 128 bf16 (16B vectors)
            {
                const uint4* src = (const uint4*)(g_h2p) + ((size_t)arow0 + PR0) * 16;
                #pragma unroll 4
                for (int i = tid; i < 132 * 16; i += 256) {
                    int r = i >> 4, c = i & 15;
                    *(uint4*)(sA + r * SA_ST + c * 8) = src[i];
                }
            }
            for (int kw = 0; kw < 5; kw++) {
                __syncthreads();
                // stage B: 64 x 128 bf16 for this tap
                {
                    const int tap = (kd * 5 + kh) * 5 + kw;
                    const uint4* src = (const uint4*)(g_wt) + (size_t)tap * 1024;
                    #pragma unroll 4
                    for (int i = tid; i < 1024; i += 256) {
                        int o = i >> 4, c = i & 15;
                        *(uint4*)(sB + o * SB_ST + c * 8) = src[i];
                    }
                }
                __syncthreads();
                // 8 k16-steps
                #pragma unroll 2
                for (int ks = 0; ks < 8; ks++) {
                    const int k0 = ks * 16;
                    uint32_t a[2][4], b[4][2];
                    #pragma unroll
                    for (int mt = 0; mt < 2; mt++) {
                        const __nv_bfloat16* p = sA + (size_t)(wm * 32 + mt * 16 + gq + kw) * SA_ST + k0 + 2 * tq;
                        a[mt][0] = *(const uint32_t*)(p);
                        a[mt][1] = *(const uint32_t*)(p + 8 * SA_ST);
                        a[mt][2] = *(const uint32_t*)(p + 8);
                        a[mt][3] = *(const uint32_t*)(p + 8 * SA_ST + 8);
                    }
                    #pragma unroll
                    for (int nt = 0; nt < 4; nt++) {
                        const __nv_bfloat16* p = sB + (size_t)(wn * 32 + nt * 8 + gq) * SB_ST + k0 + 2 * tq;
                        b[nt][0] = *(const uint32_t*)(p);
                        b[nt][1] = *(const uint32_t*)(p + 8);
                    }
                    #pragma unroll
                    for (int mt = 0; mt < 2; mt++)
                        #pragma unroll
                        for (int nt = 0; nt < 4; nt++)
                            mma16(acc[mt][nt], a[mt], b[nt]);
                }
            }
        }
    }

    // epilogue: BN3 + ReLU -> g_h3[vox][oc]
    float scv[4][2], shv[4][2];
    #pragma unroll
    for (int nt = 0; nt < 4; nt++) {
        #pragma unroll
        for (int j = 0; j < 2; j++) {
            int oc = wn * 32 + nt * 8 + 2 * tq + j;
            float s = g3[oc] * rsqrtf(v3[oc] + BNEPS);
            scv[nt][j] = s;
            shv[nt][j] = (b3b[oc] - m3[oc]) * s + bb3[oc];
        }
    }
    #pragma unroll
    for (int mt = 0; mt < 2; mt++) {
        #pragma unroll
        for (int h = 0; h < 2; h++) {
            int pm = m0 + wm * 32 + mt * 16 + gq + h * 8;
            int zp = pm / 10000, r2 = pm % 10000, yp = r2 / 100, xp = r2 % 100;
            if (zp >= 2 && zp < 6 && yp >= 2 && yp < 98 && xp >= 2 && xp < 98) {
                int vox = (zp - 2) * 9216 + (yp - 2) * 96 + (xp - 2);
                float* dst = g_h3 + (size_t)vox * 64 + wn * 32 + 2 * tq;
                #pragma unroll
                for (int nt = 0; nt < 4; nt++) {
                    float2 v;
                    v.x = fmaxf(acc[mt][nt][h * 2 + 0] * scv[nt][0] + shv[nt][0], 0.f);
                    v.y = fmaxf(acc[mt][nt][h * 2 + 1] * scv[nt][1] + shv[nt][1], 0.f);
                    *(float2*)(dst + nt * 8) = v;
                }
            }
        }
    }
}

// ---------- k5: 1x1 head (64->4) + sigmoid, thread-per-voxel ----------
__global__ __launch_bounds__(256) void k5_head(
    const float* __restrict__ w3c, const float* __restrict__ b3c, float* __restrict__ out)
{
    __shared__ float sw[256];
    const int tid = threadIdx.x;
    sw[tid] = w3c[tid];
    __syncthreads();
    const int vox = blockIdx.x * 256 + tid;
    const float4* h = (const float4*)(g_h3 + (size_t)vox * OC);
    float r0 = b3c[0], r1 = b3c[1], r2 = b3c[2], r3 = b3c[3];
    #pragma unroll
    for (int q = 0; q < 16; q++) {
        float4 v = h[q];
        const float* w0 = sw + q * 4;
        r0 += v.x * w0[0]   + v.y * w0[1]   + v.z * w0[2]   + v.w * w0[3];
        r1 += v.x * w0[64]  + v.y * w0[65]  + v.z * w0[66]  + v.w * w0[67];
        r2 += v.x * w0[128] + v.y * w0[129] + v.z * w0[130] + v.w * w0[131];
        r3 += v.x * w0[192] + v.y * w0[193] + v.z * w0[194] + v.w * w0[195];
    }
    out[0 * PP + vox] = 1.f / (1.f + expf(-r0));
    out[1 * PP + vox] = 1.f / (1.f + expf(-r1));
    out[2 * PP + vox] = 1.f / (1.f + expf(-r2));
    out[3 * PP + vox] = 1.f / (1.f + expf(-r3));
}

extern "C" void kernel_launch(void* const* d_in, const int* in_sizes, int n_in,
                              void* d_out, int out_size)
{
    const float* img = (const float*)d_in[0];
    const int* xi = (const int*)d_in[1];
    const int* yi = (const int*)d_in[2];
    const int* valid = (const int*)d_in[3];
    const float* wproj = (const float*)d_in[4];
    const float* bproj = (const float*)d_in[5];
    const float* bn1g = (const float*)d_in[6];
    const float* bn1b = (const float*)d_in[7];
    const float* bn1m = (const float*)d_in[8];
    const float* bn1v = (const float*)d_in[9];
    const float* w3a = (const float*)d_in[10];
    const float* b3a = (const float*)d_in[11];
    const float* bn2g = (const float*)d_in[12];
    const float* bn2b = (const float*)d_in[13];
    const float* bn2m = (const float*)d_in[14];
    const float* bn2v = (const float*)d_in[15];
    const float* w3b = (const float*)d_in[16];
    const float* b3b = (const float*)d_in[17];
    const float* bn3g = (const float*)d_in[18];
    const float* bn3b = (const float*)d_in[19];
    const float* bn3m = (const float*)d_in[20];
    const float* bn3v = (const float*)d_in[21];
    const float* w3c = (const float*)d_in[22];
    const float* b3c = (const float*)d_in[23];
    float* out = (float*)d_out;

    cudaFuncSetAttribute(k4_mma, cudaFuncAttributeMaxDynamicSharedMemorySize, SMEM_K4);
    k_zero<<<(PROWS * 16 + 255) / 256, 256>>>();
    k_wt<<<(125 * 8192 + 255) / 256, 256>>>(w3b);
    k1_mma<<<(NV * HWSZ) / 128, 256>>>(img, wproj, bproj, bn1g, bn1b, bn1m, bn1v);
    k2_fuse<<<PP, 128>>>(xi, yi, valid);
    k3_mma<<<PP / 128, 256>>>(w3a, b3a, bn2g, bn2b, bn2m, bn2v);
    k4_mma<<<313, 256, SMEM_K4>>>(b3b, bn3g, bn3b, bn3m, bn3v);
    k5_head<<<PP / 256, 256>>>(w3c, b3c, out);
}

// round 13
// speedup vs baseline: 4.5117x; 1.0414x over previous
#include <cuda_runtime.h>
#include <cuda_bf16.h>
#include <math.h>
#include <stdint.h>

#define NV 7
#define CIN 512
#define HH 64
#define WW 112
#define HWSZ (HH*WW)
#define DM 128
#define PP 36864
#define OC 64
#define BNEPS 1e-5f
#define PR0 512
#define PROWS 81024

__device__ float g_feat[NV * HWSZ * DM];
__device__ float g_fused[PP * DM];
__device__ __nv_bfloat16 g_h2p[(size_t)PROWS * 128];
__device__ float g_h3[PP * OC];
__device__ __nv_bfloat16 g_wt[125 * OC * DM];   // [tap][o][c], bf16

__device__ __forceinline__ float to_tf32(float f) {
    uint32_t u; asm("cvt.rna.tf32.f32 %0, %1;" : "=r"(u) : "f"(f));
    return __uint_as_float(u);
}
__device__ __forceinline__ void mma8(float* d, const uint32_t* a, const uint32_t* b) {
    asm volatile(
        "mma.sync.aligned.m16n8k8.row.col.f32.tf32.tf32.f32 "
        "{%0,%1,%2,%3},{%4,%5,%6,%7},{%8,%9},{%0,%1,%2,%3};"
        : "+f"(d[0]), "+f"(d[1]), "+f"(d[2]), "+f"(d[3])
        : "r"(a[0]), "r"(a[1]), "r"(a[2]), "r"(a[3]), "r"(b[0]), "r"(b[1]));
}
__device__ __forceinline__ void mma16(float* d, const uint32_t* a, const uint32_t* b) {
    asm volatile(
        "mma.sync.aligned.m16n8k16.row.col.f32.bf16.bf16.f32 "
        "{%0,%1,%2,%3},{%4,%5,%6,%7},{%8,%9},{%0,%1,%2,%3};"
        : "+f"(d[0]), "+f"(d[1]), "+f"(d[2]), "+f"(d[3])
        : "r"(a[0]), "r"(a[1]), "r"(a[2]), "r"(a[3]), "r"(b[0]), "r"(b[1]));
}

// ---------- zero padded volume (bf16) ----------
__global__ void k_zero() {
    size_t i = (size_t)blockIdx.x * 256 + threadIdx.x;
    if (i < (size_t)PROWS * 16)
        ((uint4*)g_h2p)[i] = make_uint4(0u, 0u, 0u, 0u);
}
// ---------- weight prep: w3b[o][c][kd][kh][kw] -> g_wt[tap][o][c] (bf16) ----------
__global__ void k_wt(const float* __restrict__ w3b) {
    int idx = blockIdx.x * 256 + threadIdx.x;
    if (idx >= 125 * 8192) return;
    int t = idx >> 13, o = (idx >> 7) & 63, c = idx & 127;
    g_wt[idx] = __float2bfloat16_rn(w3b[(size_t)(o * 128 + c) * 125 + t]);
}

// ---------- k1: projection GEMM via mma.sync tf32 + BN1 + ReLU ----------
__global__ __launch_bounds__(256) void k1_mma(
    const float* __restrict__ img, const float* __restrict__ wproj, const float* __restrict__ bproj,
    const float* __restrict__ g1, const float* __restrict__ bb1,
    const float* __restrict__ m1, const float* __restrict__ v1)
{
    __shared__ float sA[32][136];
    __shared__ float sB[128][36];
    const int tid = threadIdx.x;
    const int lane = tid & 31, wid = tid >> 5;
    const int gq = lane >> 2, tq = lane & 3;
    const int wm = wid >> 1, wn = wid & 1;
    const int m0 = blockIdx.x * 128;
    const int n = m0 / HWSZ, hw0 = m0 % HWSZ;

    float acc[2][8][4];
    #pragma unroll
    for (int mt = 0; mt < 2; mt++)
        #pragma unroll
        for (int nt = 0; nt < 8; nt++)
            #pragma unroll
            for (int q = 0; q < 4; q++) acc[mt][nt][q] = 0.f;

    for (int k0 = 0; k0 < CIN; k0 += 32) {
        __syncthreads();
        const float* asrc = img + ((size_t)n * CIN + k0) * HWSZ + hw0;
        #pragma unroll 4
        for (int i = tid; i < 4096; i += 256) {
            int kk = i >> 7, mm = i & 127;
            sA[kk][mm] = to_tf32(asrc[(size_t)kk * HWSZ + mm]);
        }
        #pragma unroll 4
        for (int i = tid; i < 4096; i += 256) {
            int d = i >> 5, kk = i & 31;
            sB[d][kk] = to_tf32(wproj[(size_t)d * CIN + k0 + kk]);
        }
        __syncthreads();
        #pragma unroll
        for (int ks = 0; ks < 4; ks++) {
            const int k = ks * 8;
            uint32_t a[2][4], b[8][2];
            #pragma unroll
            for (int mt = 0; mt < 2; mt++) {
                int row = wm * 32 + mt * 16 + gq;
                a[mt][0] = __float_as_uint(sA[k + tq][row]);
                a[mt][1] = __float_as_uint(sA[k + tq][row + 8]);
                a[mt][2] = __float_as_uint(sA[k + tq + 4][row]);
                a[mt][3] = __float_as_uint(sA[k + tq + 4][row + 8]);
            }
            #pragma unroll
            for (int nt = 0; nt < 8; nt++) {
                int dc = wn * 64 + nt * 8 + gq;
                b[nt][0] = __float_as_uint(sB[dc][k + tq]);
                b[nt][1] = __float_as_uint(sB[dc][k + tq + 4]);
            }
            #pragma unroll
            for (int mt = 0; mt < 2; mt++)
                #pragma unroll
                for (int nt = 0; nt < 8; nt++)
                    mma8(acc[mt][nt], a[mt], b[nt]);
        }
    }
    float scv[8][2], shv[8][2];
    #pragma unroll
    for (int nt = 0; nt < 8; nt++) {
        #pragma unroll
        for (int j = 0; j < 2; j++) {
            int d = wn * 64 + nt * 8 + 2 * tq + j;
            float s = g1[d] * rsqrtf(v1[d] + BNEPS);
            scv[nt][j] = s;
            shv[nt][j] = (bproj[d] - m1[d]) * s + bb1[d];
        }
    }
    #pragma unroll
    for (int mt = 0; mt < 2; mt++) {
        #pragma unroll
        for (int h = 0; h < 2; h++) {
            int m = m0 + wm * 32 + mt * 16 + gq + h * 8;
            float* dst = g_feat + (size_t)m * DM + wn * 64 + 2 * tq;
            #pragma unroll
            for (int nt = 0; nt < 8; nt++) {
                float2 v;
                v.x = fmaxf(acc[mt][nt][h * 2 + 0] * scv[nt][0] + shv[nt][0], 0.f);
                v.y = fmaxf(acc[mt][nt][h * 2 + 1] * scv[nt][1] + shv[nt][1], 0.f);
                *(float2*)(dst + nt * 8) = v;
            }
        }
    }
}

// ---------- k2: gather + masked softmax fusion (smem-broadcast indices) ----------
__global__ __launch_bounds__(128) void k2_fuse(
    const int* __restrict__ xi, const int* __restrict__ yi, const int* __restrict__ valid)
{
    __shared__ int slin[NV];
    const int p = blockIdx.x, d = threadIdx.x;
    if (d < NV) {
        int v = valid[d * PP + p];
        slin[d] = v ? (yi[d * PP + p] * WW + xi[d * PP + p]) : -1;
    }
    __syncthreads();
    float vv[NV];
    #pragma unroll
    for (int n = 0; n < NV; n++) {
        int lin = slin[n];
        float val = 0.f;
        if (lin >= 0)
            val = g_feat[((size_t)(n * HWSZ + lin)) * DM + d];
        vv[n] = val;
    }
    float mx = vv[0];
    #pragma unroll
    for (int n = 1; n < NV; n++) mx = fmaxf(mx, vv[n]);
    float s = 0.f, ws = 0.f;
    #pragma unroll
    for (int n = 0; n < NV; n++) { float e = __expf(vv[n] - mx); s += e; ws += e * vv[n]; }
    g_fused[(size_t)p * DM + d] = ws / s;
}

// ---------- k3: 1x1 GEMM via mma.sync tf32 + BN2 + ReLU -> padded bf16 volume ----------
__global__ __launch_bounds__(256) void k3_mma(
    const float* __restrict__ w3a, const float* __restrict__ b3a,
    const float* __restrict__ g2, const float* __restrict__ bb2,
    const float* __restrict__ m2, const float* __restrict__ v2)
{
    __shared__ float sA[128][36];
    __shared__ float sB[128][36];
    const int tid = threadIdx.x;
    const int lane = tid & 31, wid = tid >> 5;
    const int gq = lane >> 2, tq = lane & 3;
    const int wm = wid >> 1, wn = wid & 1;
    const int m0 = blockIdx.x * 128;

    float acc[2][8][4];
    #pragma unroll
    for (int mt = 0; mt < 2; mt++)
        #pragma unroll
        for (int nt = 0; nt < 8; nt++)
            #pragma unroll
            for (int q = 0; q < 4; q++) acc[mt][nt][q] = 0.f;

    for (int k0 = 0; k0 < DM; k0 += 32) {
        __syncthreads();
        #pragma unroll 4
        for (int i = tid; i < 4096; i += 256) {
            int mm = i >> 5, kk = i & 31;
            sA[mm][kk] = to_tf32(g_fused[(size_t)(m0 + mm) * DM + k0 + kk]);
            sB[mm][kk] = to_tf32(w3a[(size_t)mm * DM + k0 + kk]);
        }
        __syncthreads();
        #pragma unroll
        for (int ks = 0; ks < 4; ks++) {
            const int k = ks * 8;
            uint32_t a[2][4], b[8][2];
            #pragma unroll
            for (int mt = 0; mt < 2; mt++) {
                const float* p = &sA[wm * 32 + mt * 16 + gq][k + tq];
                a[mt][0] = __float_as_uint(p[0]);
                a[mt][1] = __float_as_uint(p[8 * 36]);
                a[mt][2] = __float_as_uint(p[4]);
                a[mt][3] = __float_as_uint(p[8 * 36 + 4]);
            }
            #pragma unroll
            for (int nt = 0; nt < 8; nt++) {
                const float* p = &sB[wn * 64 + nt * 8 + gq][k + tq];
                b[nt][0] = __float_as_uint(p[0]);
                b[nt][1] = __float_as_uint(p[4]);
            }
            #pragma unroll
            for (int mt = 0; mt < 2; mt++)
                #pragma unroll
                for (int nt = 0; nt < 8; nt++)
                    mma8(acc[mt][nt], a[mt], b[nt]);
        }
    }
    float scv[8][2], shv[8][2];
    #pragma unroll
    for (int nt = 0; nt < 8; nt++) {
        #pragma unroll
        for (int j = 0; j < 2; j++) {
            int d = wn * 64 + nt * 8 + 2 * tq + j;
            float s = g2[d] * rsqrtf(v2[d] + BNEPS);
            scv[nt][j] = s;
            shv[nt][j] = (b3a[d] - m2[d]) * s + bb2[d];
        }
    }
    #pragma unroll
    for (int mt = 0; mt < 2; mt++) {
        #pragma unroll
        for (int h = 0; h < 2; h++) {
            int m = m0 + wm * 32 + mt * 16 + gq + h * 8;
            int z = m / 9216, rem = m % 9216, y = rem / 96, x = rem % 96;
            size_t pm = (size_t)(z + 2) * 10000 + (y + 2) * 100 + (x + 2) + PR0;
            __nv_bfloat16* dst = g_h2p + pm * 128 + wn * 64 + 2 * tq;
            #pragma unroll
            for (int nt = 0; nt < 8; nt++) {
                float vx = fmaxf(acc[mt][nt][h * 2 + 0] * scv[nt][0] + shv[nt][0], 0.f);
                float vy = fmaxf(acc[mt][nt][h * 2 + 1] * scv[nt][1] + shv[nt][1], 0.f);
                *(__nv_bfloat162*)(dst + nt * 8) = __floats2bfloat162_rn(vx, vy);
            }
        }
    }
}

// ---------- k4: 5x5x5 conv via mma.sync bf16 implicit GEMM ----------
// 4 warps (4M x 1N), warp = m32 x n64: 192 B LDS per MMA (vs 256 at m32n32).
#define SA_ST 136
#define SB_ST 136
#define SA_BYTES (132 * SA_ST * 2)      // 35904
#define SB_BYTES (64 * SB_ST * 2)       // 17408
#define SMEM_K4 (SA_BYTES + SB_BYTES)   // 53312
__global__ __launch_bounds__(128, 4) void k4_mma(
    const float* __restrict__ b3b, const float* __restrict__ g3,
    const float* __restrict__ bb3, const float* __restrict__ m3, const float* __restrict__ v3)
{
    extern __shared__ __align__(16) char smem[];
    __nv_bfloat16* sA = (__nv_bfloat16*)smem;                 // [132][136]
    __nv_bfloat16* sB = (__nv_bfloat16*)(smem + SA_BYTES);    // [64][136]

    const int tid = threadIdx.x;
    const int lane = tid & 31, wm = tid >> 5;   // 4 warps, all-M split
    const int gq = lane >> 2, tq = lane & 3;
    const int m0 = 20000 + blockIdx.x * 128;

    float acc[2][8][4];
    #pragma unroll
    for (int mt = 0; mt < 2; mt++)
        #pragma unroll
        for (int nt = 0; nt < 8; nt++)
            #pragma unroll
            for (int q = 0; q < 4; q++) acc[mt][nt][q] = 0.f;

    for (int kd = 0; kd < 5; kd++) {
        for (int kh = 0; kh < 5; kh++) {
            const int arow0 = m0 + (kd - 2) * 10000 + (kh - 2) * 100 - 2;
            if (arow0 >= 60000 || arow0 + 131 < 20000) continue;  // all-zero slab
            __syncthreads();
            // stage A: 132 rows x 128 bf16 (16B vectors)
            {
                const uint4* src = (const uint4*)(g_h2p) + ((size_t)arow0 + PR0) * 16;
                #pragma unroll 4
                for (int i = tid; i < 132 * 16; i += 128) {
                    int r = i >> 4, c = i & 15;
                    *(uint4*)(sA + r * SA_ST + c * 8) = src[i];
                }
            }
            for (int kw = 0; kw < 5; kw++) {
                __syncthreads();
                // stage B: 64 x 128 bf16 for this tap
                {
                    const int tap = (kd * 5 + kh) * 5 + kw;
                    const uint4* src = (const uint4*)(g_wt) + (size_t)tap * 1024;
                    #pragma unroll 4
                    for (int i = tid; i < 1024; i += 128) {
                        int o = i >> 4, c = i & 15;
                        *(uint4*)(sB + o * SB_ST + c * 8) = src[i];
                    }
                }
                __syncthreads();
                // 8 k16-steps, warp covers n=0..63
                #pragma unroll 2
                for (int ks = 0; ks < 8; ks++) {
                    const int k0 = ks * 16;
                    uint32_t a[2][4], b[8][2];
                    #pragma unroll
                    for (int mt = 0; mt < 2; mt++) {
                        const __nv_bfloat16* p = sA + (size_t)(wm * 32 + mt * 16 + gq + kw) * SA_ST + k0 + 2 * tq;
                        a[mt][0] = *(const uint32_t*)(p);
                        a[mt][1] = *(const uint32_t*)(p + 8 * SA_ST);
                        a[mt][2] = *(const uint32_t*)(p + 8);
                        a[mt][3] = *(const uint32_t*)(p + 8 * SA_ST + 8);
                    }
                    #pragma unroll
                    for (int nt = 0; nt < 8; nt++) {
                        const __nv_bfloat16* p = sB + (size_t)(nt * 8 + gq) * SB_ST + k0 + 2 * tq;
                        b[nt][0] = *(const uint32_t*)(p);
                        b[nt][1] = *(const uint32_t*)(p + 8);
                    }
                    #pragma unroll
                    for (int mt = 0; mt < 2; mt++)
                        #pragma unroll
                        for (int nt = 0; nt < 8; nt++)
                            mma16(acc[mt][nt], a[mt], b[nt]);
                }
            }
        }
    }

    // epilogue: BN3 + ReLU -> g_h3[vox][oc]
    float scv[8][2], shv[8][2];
    #pragma unroll
    for (int nt = 0; nt < 8; nt++) {
        #pragma unroll
        for (int j = 0; j < 2; j++) {
            int oc = nt * 8 + 2 * tq + j;
            float s = g3[oc] * rsqrtf(v3[oc] + BNEPS);
            scv[nt][j] = s;
            shv[nt][j] = (b3b[oc] - m3[oc]) * s + bb3[oc];
        }
    }
    #pragma unroll
    for (int mt = 0; mt < 2; mt++) {
        #pragma unroll
        for (int h = 0; h < 2; h++) {
            int pm = m0 + wm * 32 + mt * 16 + gq + h * 8;
            int zp = pm / 10000, r2 = pm % 10000, yp = r2 / 100, xp = r2 % 100;
            if (zp >= 2 && zp < 6 && yp >= 2 && yp < 98 && xp >= 2 && xp < 98) {
                int vox = (zp - 2) * 9216 + (yp - 2) * 96 + (xp - 2);
                float* dst = g_h3 + (size_t)vox * 64 + 2 * tq;
                #pragma unroll
                for (int nt = 0; nt < 8; nt++) {
                    float2 v;
                    v.x = fmaxf(acc[mt][nt][h * 2 + 0] * scv[nt][0] + shv[nt][0], 0.f);
                    v.y = fmaxf(acc[mt][nt][h * 2 + 1] * scv[nt][1] + shv[nt][1], 0.f);
                    *(float2*)(dst + nt * 8) = v;
                }
            }
        }
    }
}

// ---------- k5: 1x1 head (64->4) + sigmoid, thread-per-voxel ----------
__global__ __launch_bounds__(256) void k5_head(
    const float* __restrict__ w3c, const float* __restrict__ b3c, float* __restrict__ out)
{
    __shared__ float sw[256];
    const int tid = threadIdx.x;
    sw[tid] = w3c[tid];
    __syncthreads();
    const int vox = blockIdx.x * 256 + tid;
    const float4* h = (const float4*)(g_h3 + (size_t)vox * OC);
    float r0 = b3c[0], r1 = b3c[1], r2 = b3c[2], r3 = b3c[3];
    #pragma unroll
    for (int q = 0; q < 16; q++) {
        float4 v = h[q];
        const float* w0 = sw + q * 4;
        r0 += v.x * w0[0]   + v.y * w0[1]   + v.z * w0[2]   + v.w * w0[3];
        r1 += v.x * w0[64]  + v.y * w0[65]  + v.z * w0[66]  + v.w * w0[67];
        r2 += v.x * w0[128] + v.y * w0[129] + v.z * w0[130] + v.w * w0[131];
        r3 += v.x * w0[192] + v.y * w0[193] + v.z * w0[194] + v.w * w0[195];
    }
    out[0 * PP + vox] = 1.f / (1.f + __expf(-r0));
    out[1 * PP + vox] = 1.f / (1.f + __expf(-r1));
    out[2 * PP + vox] = 1.f / (1.f + __expf(-r2));
    out[3 * PP + vox] = 1.f / (1.f + __expf(-r3));
}

extern "C" void kernel_launch(void* const* d_in, const int* in_sizes, int n_in,
                              void* d_out, int out_size)
{
    const float* img = (const float*)d_in[0];
    const int* xi = (const int*)d_in[1];
    const int* yi = (const int*)d_in[2];
    const int* valid = (const int*)d_in[3];
    const float* wproj = (const float*)d_in[4];
    const float* bproj = (const float*)d_in[5];
    const float* bn1g = (const float*)d_in[6];
    const float* bn1b = (const float*)d_in[7];
    const float* bn1m = (const float*)d_in[8];
    const float* bn1v = (const float*)d_in[9];
    const float* w3a = (const float*)d_in[10];
    const float* b3a = (const float*)d_in[11];
    const float* bn2g = (const float*)d_in[12];
    const float* bn2b = (const float*)d_in[13];
    const float* bn2m = (const float*)d_in[14];
    const float* bn2v = (const float*)d_in[15];
    const float* w3b = (const float*)d_in[16];
    const float* b3b = (const float*)d_in[17];
    const float* bn3g = (const float*)d_in[18];
    const float* bn3b = (const float*)d_in[19];
    const float* bn3m = (const float*)d_in[20];
    const float* bn3v = (const float*)d_in[21];
    const float* w3c = (const float*)d_in[22];
    const float* b3c = (const float*)d_in[23];
    float* out = (float*)d_out;

    cudaFuncSetAttribute(k4_mma, cudaFuncAttributeMaxDynamicSharedMemorySize, SMEM_K4);
    k_zero<<<(PROWS * 16 + 255) / 256, 256>>>();
    k_wt<<<(125 * 8192 + 255) / 256, 256>>>(w3b);
    k1_mma<<<(NV * HWSZ) / 128, 256>>>(img, wproj, bproj, bn1g, bn1b, bn1m, bn1v);
    k2_fuse<<<PP, 128>>>(xi, yi, valid);
    k3_mma<<<PP / 128, 256>>>(w3a, b3a, bn2g, bn2b, bn2m, bn2v);
    k4_mma<<<313, 128, SMEM_K4>>>(b3b, bn3g, bn3b, bn3m, bn3v);
    k5_head<<<PP / 256, 256>>>(w3c, b3c, out);
}

// round 14
// speedup vs baseline: 4.6963x; 1.0409x over previous
#include <cuda_runtime.h>
#include <cuda_bf16.h>
#include <math.h>
#include <stdint.h>

#define NV 7
#define CIN 512
#define HH 64
#define WW 112
#define HWSZ (HH*WW)
#define DM 128
#define PP 36864
#define OC 64
#define BNEPS 1e-5f
#define PR0 512
#define PROWS 81024

__device__ float g_feat[NV * HWSZ * DM];
__device__ float g_fused[PP * DM];
__device__ __nv_bfloat16 g_h2p[(size_t)PROWS * 128];
__device__ float g_h3[PP * OC];
__device__ __nv_bfloat16 g_wt[125 * OC * DM];   // [tap][o][c], bf16

__device__ __forceinline__ float to_tf32(float f) {
    uint32_t u; asm("cvt.rna.tf32.f32 %0, %1;" : "=r"(u) : "f"(f));
    return __uint_as_float(u);
}
__device__ __forceinline__ uint32_t smem_u32(const void* p) {
    uint32_t a;
    asm("{ .reg .u64 t; cvta.to.shared.u64 t, %1; cvt.u32.u64 %0, t; }" : "=r"(a) : "l"(p));
    return a;
}
__device__ __forceinline__ void cp16(uint32_t dst, const void* src) {
    asm volatile("cp.async.cg.shared.global [%0], [%1], 16;" :: "r"(dst), "l"(src));
}
__device__ __forceinline__ void mma8(float* d, const uint32_t* a, const uint32_t* b) {
    asm volatile(
        "mma.sync.aligned.m16n8k8.row.col.f32.tf32.tf32.f32 "
        "{%0,%1,%2,%3},{%4,%5,%6,%7},{%8,%9},{%0,%1,%2,%3};"
        : "+f"(d[0]), "+f"(d[1]), "+f"(d[2]), "+f"(d[3])
        : "r"(a[0]), "r"(a[1]), "r"(a[2]), "r"(a[3]), "r"(b[0]), "r"(b[1]));
}
__device__ __forceinline__ void mma16(float* d, const uint32_t* a, const uint32_t* b) {
    asm volatile(
        "mma.sync.aligned.m16n8k16.row.col.f32.bf16.bf16.f32 "
        "{%0,%1,%2,%3},{%4,%5,%6,%7},{%8,%9},{%0,%1,%2,%3};"
        : "+f"(d[0]), "+f"(d[1]), "+f"(d[2]), "+f"(d[3])
        : "r"(a[0]), "r"(a[1]), "r"(a[2]), "r"(a[3]), "r"(b[0]), "r"(b[1]));
}

// ---------- zero halo of padded volume (interior is overwritten by k3 every launch) ----------
__global__ void k_zero() {
    size_t i = (size_t)blockIdx.x * 256 + threadIdx.x;
    if (i >= (size_t)PROWS * 16) return;
    int r = (int)(i >> 4);
    int pr = r - PR0;
    if (pr >= 0 && pr < 80000) {
        int zp = pr / 10000, rem = pr % 10000, yp = rem / 100, xp = rem % 100;
        if (zp >= 2 && zp < 6 && yp >= 2 && yp < 98 && xp >= 2 && xp < 98) return;
    }
    ((uint4*)g_h2p)[i] = make_uint4(0u, 0u, 0u, 0u);
}
// ---------- weight prep: w3b[o][c][kd][kh][kw] -> g_wt[tap][o][c] (bf16) ----------
__global__ void k_wt(const float* __restrict__ w3b) {
    int idx = blockIdx.x * 256 + threadIdx.x;
    if (idx >= 125 * 8192) return;
    int t = idx >> 13, o = (idx >> 7) & 63, c = idx & 127;
    g_wt[idx] = __float2bfloat16_rn(w3b[(size_t)(o * 128 + c) * 125 + t]);
}

// ---------- k1: projection GEMM via mma.sync tf32 + BN1 + ReLU ----------
__global__ __launch_bounds__(256) void k1_mma(
    const float* __restrict__ img, const float* __restrict__ wproj, const float* __restrict__ bproj,
    const float* __restrict__ g1, const float* __restrict__ bb1,
    const float* __restrict__ m1, const float* __restrict__ v1)
{
    __shared__ float sA[32][136];
    __shared__ float sB[128][36];
    const int tid = threadIdx.x;
    const int lane = tid & 31, wid = tid >> 5;
    const int gq = lane >> 2, tq = lane & 3;
    const int wm = wid >> 1, wn = wid & 1;
    const int m0 = blockIdx.x * 128;
    const int n = m0 / HWSZ, hw0 = m0 % HWSZ;

    float acc[2][8][4];
    #pragma unroll
    for (int mt = 0; mt < 2; mt++)
        #pragma unroll
        for (int nt = 0; nt < 8; nt++)
            #pragma unroll
            for (int q = 0; q < 4; q++) acc[mt][nt][q] = 0.f;

    for (int k0 = 0; k0 < CIN; k0 += 32) {
        __syncthreads();
        const float* asrc = img + ((size_t)n * CIN + k0) * HWSZ + hw0;
        #pragma unroll 4
        for (int i = tid; i < 4096; i += 256) {
            int kk = i >> 7, mm = i & 127;
            sA[kk][mm] = to_tf32(asrc[(size_t)kk * HWSZ + mm]);
        }
        #pragma unroll 4
        for (int i = tid; i < 4096; i += 256) {
            int d = i >> 5, kk = i & 31;
            sB[d][kk] = to_tf32(wproj[(size_t)d * CIN + k0 + kk]);
        }
        __syncthreads();
        #pragma unroll
        for (int ks = 0; ks < 4; ks++) {
            const int k = ks * 8;
            uint32_t a[2][4], b[8][2];
            #pragma unroll
            for (int mt = 0; mt < 2; mt++) {
                int row = wm * 32 + mt * 16 + gq;
                a[mt][0] = __float_as_uint(sA[k + tq][row]);
                a[mt][1] = __float_as_uint(sA[k + tq][row + 8]);
                a[mt][2] = __float_as_uint(sA[k + tq + 4][row]);
                a[mt][3] = __float_as_uint(sA[k + tq + 4][row + 8]);
            }
            #pragma unroll
            for (int nt = 0; nt < 8; nt++) {
                int dc = wn * 64 + nt * 8 + gq;
                b[nt][0] = __float_as_uint(sB[dc][k + tq]);
                b[nt][1] = __float_as_uint(sB[dc][k + tq + 4]);
            }
            #pragma unroll
            for (int mt = 0; mt < 2; mt++)
                #pragma unroll
                for (int nt = 0; nt < 8; nt++)
                    mma8(acc[mt][nt], a[mt], b[nt]);
        }
    }
    float scv[8][2], shv[8][2];
    #pragma unroll
    for (int nt = 0; nt < 8; nt++) {
        #pragma unroll
        for (int j = 0; j < 2; j++) {
            int d = wn * 64 + nt * 8 + 2 * tq + j;
            float s = g1[d] * rsqrtf(v1[d] + BNEPS);
            scv[nt][j] = s;
            shv[nt][j] = (bproj[d] - m1[d]) * s + bb1[d];
        }
    }
    #pragma unroll
    for (int mt = 0; mt < 2; mt++) {
        #pragma unroll
        for (int h = 0; h < 2; h++) {
            int m = m0 + wm * 32 + mt * 16 + gq + h * 8;
            float* dst = g_feat + (size_t)m * DM + wn * 64 + 2 * tq;
            #pragma unroll
            for (int nt = 0; nt < 8; nt++) {
                float2 v;
                v.x = fmaxf(acc[mt][nt][h * 2 + 0] * scv[nt][0] + shv[nt][0], 0.f);
                v.y = fmaxf(acc[mt][nt][h * 2 + 1] * scv[nt][1] + shv[nt][1], 0.f);
                *(float2*)(dst + nt * 8) = v;
            }
        }
    }
}

// ---------- k2: gather + masked softmax fusion (smem-broadcast indices) ----------
__global__ __launch_bounds__(128) void k2_fuse(
    const int* __restrict__ xi, const int* __restrict__ yi, const int* __restrict__ valid)
{
    __shared__ int slin[NV];
    const int p = blockIdx.x, d = threadIdx.x;
    if (d < NV) {
        int v = valid[d * PP + p];
        slin[d] = v ? (yi[d * PP + p] * WW + xi[d * PP + p]) : -1;
    }
    __syncthreads();
    float vv[NV];
    #pragma unroll
    for (int n = 0; n < NV; n++) {
        int lin = slin[n];
        float val = 0.f;
        if (lin >= 0)
            val = g_feat[((size_t)(n * HWSZ + lin)) * DM + d];
        vv[n] = val;
    }
    float mx = vv[0];
    #pragma unroll
    for (int n = 1; n < NV; n++) mx = fmaxf(mx, vv[n]);
    float s = 0.f, ws = 0.f;
    #pragma unroll
    for (int n = 0; n < NV; n++) { float e = __expf(vv[n] - mx); s += e; ws += e * vv[n]; }
    g_fused[(size_t)p * DM + d] = ws / s;
}

// ---------- k3: 1x1 GEMM via mma.sync tf32 + BN2 + ReLU -> padded bf16 volume ----------
__global__ __launch_bounds__(256) void k3_mma(
    const float* __restrict__ w3a, const float* __restrict__ b3a,
    const float* __restrict__ g2, const float* __restrict__ bb2,
    const float* __restrict__ m2, const float* __restrict__ v2)
{
    __shared__ float sA[128][36];
    __shared__ float sB[128][36];
    const int tid = threadIdx.x;
    const int lane = tid & 31, wid = tid >> 5;
    const int gq = lane >> 2, tq = lane & 3;
    const int wm = wid >> 1, wn = wid & 1;
    const int m0 = blockIdx.x * 128;

    float acc[2][8][4];
    #pragma unroll
    for (int mt = 0; mt < 2; mt++)
        #pragma unroll
        for (int nt = 0; nt < 8; nt++)
            #pragma unroll
            for (int q = 0; q < 4; q++) acc[mt][nt][q] = 0.f;

    for (int k0 = 0; k0 < DM; k0 += 32) {
        __syncthreads();
        #pragma unroll 4
        for (int i = tid; i < 4096; i += 256) {
            int mm = i >> 5, kk = i & 31;
            sA[mm][kk] = to_tf32(g_fused[(size_t)(m0 + mm) * DM + k0 + kk]);
            sB[mm][kk] = to_tf32(w3a[(size_t)mm * DM + k0 + kk]);
        }
        __syncthreads();
        #pragma unroll
        for (int ks = 0; ks < 4; ks++) {
            const int k = ks * 8;
            uint32_t a[2][4], b[8][2];
            #pragma unroll
            for (int mt = 0; mt < 2; mt++) {
                const float* p = &sA[wm * 32 + mt * 16 + gq][k + tq];
                a[mt][0] = __float_as_uint(p[0]);
                a[mt][1] = __float_as_uint(p[8 * 36]);
                a[mt][2] = __float_as_uint(p[4]);
                a[mt][3] = __float_as_uint(p[8 * 36 + 4]);
            }
            #pragma unroll
            for (int nt = 0; nt < 8; nt++) {
                const float* p = &sB[wn * 64 + nt * 8 + gq][k + tq];
                b[nt][0] = __float_as_uint(p[0]);
                b[nt][1] = __float_as_uint(p[4]);
            }
            #pragma unroll
            for (int mt = 0; mt < 2; mt++)
                #pragma unroll
                for (int nt = 0; nt < 8; nt++)
                    mma8(acc[mt][nt], a[mt], b[nt]);
        }
    }
    float scv[8][2], shv[8][2];
    #pragma unroll
    for (int nt = 0; nt < 8; nt++) {
        #pragma unroll
        for (int j = 0; j < 2; j++) {
            int d = wn * 64 + nt * 8 + 2 * tq + j;
            float s = g2[d] * rsqrtf(v2[d] + BNEPS);
            scv[nt][j] = s;
            shv[nt][j] = (b3a[d] - m2[d]) * s + bb2[d];
        }
    }
    #pragma unroll
    for (int mt = 0; mt < 2; mt++) {
        #pragma unroll
        for (int h = 0; h < 2; h++) {
            int m = m0 + wm * 32 + mt * 16 + gq + h * 8;
            int z = m / 9216, rem = m % 9216, y = rem / 96, x = rem % 96;
            size_t pm = (size_t)(z + 2) * 10000 + (y + 2) * 100 + (x + 2) + PR0;
            __nv_bfloat16* dst = g_h2p + pm * 128 + wn * 64 + 2 * tq;
            #pragma unroll
            for (int nt = 0; nt < 8; nt++) {
                float vx = fmaxf(acc[mt][nt][h * 2 + 0] * scv[nt][0] + shv[nt][0], 0.f);
                float vy = fmaxf(acc[mt][nt][h * 2 + 1] * scv[nt][1] + shv[nt][1], 0.f);
                *(__nv_bfloat162*)(dst + nt * 8) = __floats2bfloat162_rn(vx, vy);
            }
        }
    }
}

// ---------- k4: 5x5x5 conv via mma.sync bf16, cp.async double-buffered B ----------
#define SA_ST 136
#define SB_ST 136
#define SA_BYTES (132 * SA_ST * 2)      // 35904
#define SB_BYTES (64 * SB_ST * 2)       // 17408
#define SMEM_K4 (SA_BYTES + 2 * SB_BYTES)   // 70720
__global__ __launch_bounds__(128, 3) void k4_mma(
    const float* __restrict__ b3b, const float* __restrict__ g3,
    const float* __restrict__ bb3, const float* __restrict__ m3, const float* __restrict__ v3)
{
    extern __shared__ __align__(16) char smem[];
    __nv_bfloat16* sA = (__nv_bfloat16*)smem;                          // [132][136]
    const uint32_t sbase = smem_u32(smem);
    const uint32_t sAu = sbase;
    const uint32_t sBu0 = sbase + SA_BYTES;

    const int tid = threadIdx.x;
    const int lane = tid & 31, wm = tid >> 5;   // 4 warps, all-M split
    const int gq = lane >> 2, tq = lane & 3;
    const int m0 = 20000 + blockIdx.x * 128;

    float acc[2][8][4];
    #pragma unroll
    for (int mt = 0; mt < 2; mt++)
        #pragma unroll
        for (int nt = 0; nt < 8; nt++)
            #pragma unroll
            for (int q = 0; q < 4; q++) acc[mt][nt][q] = 0.f;

    for (int kd = 0; kd < 5; kd++) {
        for (int kh = 0; kh < 5; kh++) {
            const int arow0 = m0 + (kd - 2) * 10000 + (kh - 2) * 100 - 2;
            if (arow0 >= 60000 || arow0 + 131 < 20000) continue;  // all-zero slab
            __syncthreads();   // previous slab's compute done (sA, sB free)
            // issue A: 132 rows x 128 bf16 (2112 x 16B)
            {
                const uint4* src = (const uint4*)(g_h2p) + ((size_t)arow0 + PR0) * 16;
                #pragma unroll 4
                for (int i = tid; i < 132 * 16; i += 128)
                    cp16(sAu + (uint32_t)((i >> 4) * SA_ST * 2 + (i & 15) * 16), src + i);
            }
            // issue B[kw=0] into buf0
            {
                const int tap0 = (kd * 5 + kh) * 5;
                const uint4* src = (const uint4*)(g_wt) + (size_t)tap0 * 1024;
                #pragma unroll 4
                for (int i = tid; i < 1024; i += 128)
                    cp16(sBu0 + (uint32_t)((i >> 4) * SB_ST * 2 + (i & 15) * 16), src + i);
            }
            asm volatile("cp.async.commit_group;" ::: "memory");
            asm volatile("cp.async.wait_group 0;" ::: "memory");
            __syncthreads();
            for (int kw = 0; kw < 5; kw++) {
                const uint32_t curB = sBu0 + (uint32_t)(kw & 1) * SB_BYTES;
                // prefetch B[kw+1] into the other buffer (overlaps compute below)
                if (kw < 4) {
                    const int tap = (kd * 5 + kh) * 5 + kw + 1;
                    const uint4* src = (const uint4*)(g_wt) + (size_t)tap * 1024;
                    const uint32_t nxtB = sBu0 + (uint32_t)((kw + 1) & 1) * SB_BYTES;
                    #pragma unroll 4
                    for (int i = tid; i < 1024; i += 128)
                        cp16(nxtB + (uint32_t)((i >> 4) * SB_ST * 2 + (i & 15) * 16), src + i);
                    asm volatile("cp.async.commit_group;" ::: "memory");
                }
                const __nv_bfloat16* sBk = (const __nv_bfloat16*)smem + (SA_BYTES / 2) + (kw & 1) * (SB_BYTES / 2);
                // 8 k16-steps, warp covers n=0..63
                #pragma unroll 2
                for (int ks = 0; ks < 8; ks++) {
                    const int k0 = ks * 16;
                    uint32_t a[2][4], b[8][2];
                    #pragma unroll
                    for (int mt = 0; mt < 2; mt++) {
                        const __nv_bfloat16* p = sA + (size_t)(wm * 32 + mt * 16 + gq + kw) * SA_ST + k0 + 2 * tq;
                        a[mt][0] = *(const uint32_t*)(p);
                        a[mt][1] = *(const uint32_t*)(p + 8 * SA_ST);
                        a[mt][2] = *(const uint32_t*)(p + 8);
                        a[mt][3] = *(const uint32_t*)(p + 8 * SA_ST + 8);
                    }
                    #pragma unroll
                    for (int nt = 0; nt < 8; nt++) {
                        const __nv_bfloat16* p = sBk + (size_t)(nt * 8 + gq) * SB_ST + k0 + 2 * tq;
                        b[nt][0] = *(const uint32_t*)(p);
                        b[nt][1] = *(const uint32_t*)(p + 8);
                    }
                    #pragma unroll
                    for (int mt = 0; mt < 2; mt++)
                        #pragma unroll
                        for (int nt = 0; nt < 8; nt++)
                            mma16(acc[mt][nt], a[mt], b[nt]);
                }
                if (kw < 4) {
                    asm volatile("cp.async.wait_group 0;" ::: "memory");
                    __syncthreads();
                }
            }
        }
    }

    // epilogue: BN3 + ReLU -> g_h3[vox][oc]
    float scv[8][2], shv[8][2];
    #pragma unroll
    for (int nt = 0; nt < 8; nt++) {
        #pragma unroll
        for (int j = 0; j < 2; j++) {
            int oc = nt * 8 + 2 * tq + j;
            float s = g3[oc] * rsqrtf(v3[oc] + BNEPS);
            scv[nt][j] = s;
            shv[nt][j] = (b3b[oc] - m3[oc]) * s + bb3[oc];
        }
    }
    #pragma unroll
    for (int mt = 0; mt < 2; mt++) {
        #pragma unroll
        for (int h = 0; h < 2; h++) {
            int pm = m0 + wm * 32 + mt * 16 + gq + h * 8;
            int zp = pm / 10000, r2 = pm % 10000, yp = r2 / 100, xp = r2 % 100;
            if (zp >= 2 && zp < 6 && yp >= 2 && yp < 98 && xp >= 2 && xp < 98) {
                int vox = (zp - 2) * 9216 + (yp - 2) * 96 + (xp - 2);
                float* dst = g_h3 + (size_t)vox * 64 + 2 * tq;
                #pragma unroll
                for (int nt = 0; nt < 8; nt++) {
                    float2 v;
                    v.x = fmaxf(acc[mt][nt][h * 2 + 0] * scv[nt][0] + shv[nt][0], 0.f);
                    v.y = fmaxf(acc[mt][nt][h * 2 + 1] * scv[nt][1] + shv[nt][1], 0.f);
                    *(float2*)(dst + nt * 8) = v;
                }
            }
        }
    }
}

// ---------- k5: 1x1 head (64->4) + sigmoid, thread-per-voxel ----------
__global__ __launch_bounds__(256) void k5_head(
    const float* __restrict__ w3c, const float* __restrict__ b3c, float* __restrict__ out)
{
    __shared__ float sw[256];
    const int tid = threadIdx.x;
    sw[tid] = w3c[tid];
    __syncthreads();
    const int vox = blockIdx.x * 256 + tid;
    const float4* h = (const float4*)(g_h3 + (size_t)vox * OC);
    float r0 = b3c[0], r1 = b3c[1], r2 = b3c[2], r3 = b3c[3];
    #pragma unroll
    for (int q = 0; q < 16; q++) {
        float4 v = h[q];
        const float* w0 = sw + q * 4;
        r0 += v.x * w0[0]   + v.y * w0[1]   + v.z * w0[2]   + v.w * w0[3];
        r1 += v.x * w0[64]  + v.y * w0[65]  + v.z * w0[66]  + v.w * w0[67];
        r2 += v.x * w0[128] + v.y * w0[129] + v.z * w0[130] + v.w * w0[131];
        r3 += v.x * w0[192] + v.y * w0[193] + v.z * w0[194] + v.w * w0[195];
    }
    out[0 * PP + vox] = 1.f / (1.f + __expf(-r0));
    out[1 * PP + vox] = 1.f / (1.f + __expf(-r1));
    out[2 * PP + vox] = 1.f / (1.f + __expf(-r2));
    out[3 * PP + vox] = 1.f / (1.f + __expf(-r3));
}

extern "C" void kernel_launch(void* const* d_in, const int* in_sizes, int n_in,
                              void* d_out, int out_size)
{
    const float* img = (const float*)d_in[0];
    const int* xi = (const int*)d_in[1];
    const int* yi = (const int*)d_in[2];
    const int* valid = (const int*)d_in[3];
    const float* wproj = (const float*)d_in[4];
    const float* bproj = (const float*)d_in[5];
    const float* bn1g = (const float*)d_in[6];
    const float* bn1b = (const float*)d_in[7];
    const float* bn1m = (const float*)d_in[8];
    const float* bn1v = (const float*)d_in[9];
    const float* w3a = (const float*)d_in[10];
    const float* b3a = (const float*)d_in[11];
    const float* bn2g = (const float*)d_in[12];
    const float* bn2b = (const float*)d_in[13];
    const float* bn2m = (const float*)d_in[14];
    const float* bn2v = (const float*)d_in[15];
    const float* w3b = (const float*)d_in[16];
    const float* b3b = (const float*)d_in[17];
    const float* bn3g = (const float*)d_in[18];
    const float* bn3b = (const float*)d_in[19];
    const float* bn3m = (const float*)d_in[20];
    const float* bn3v = (const float*)d_in[21];
    const float* w3c = (const float*)d_in[22];
    const float* b3c = (const float*)d_in[23];
    float* out = (float*)d_out;

    cudaFuncSetAttribute(k4_mma, cudaFuncAttributeMaxDynamicSharedMemorySize, SMEM_K4);
    k_zero<<<(PROWS * 16 + 255) / 256, 256>>>();
    k_wt<<<(125 * 8192 + 255) / 256, 256>>>(w3b);
    k1_mma<<<(NV * HWSZ) / 128, 256>>>(img, wproj, bproj, bn1g, bn1b, bn1m, bn1v);
    k2_fuse<<<PP, 128>>>(xi, yi, valid);
    k3_mma<<<PP / 128, 256>>>(w3a, b3a, bn2g, bn2b, bn2m, bn2v);
    k4_mma<<<313, 128, SMEM_K4>>>(b3b, bn3g, bn3b, bn3m, bn3v);
    k5_head<<<PP / 256, 256>>>(w3c, b3c, out);
}

// round 15
// speedup vs baseline: 6.3669x; 1.3557x over previous
#include <cuda_runtime.h>
#include <cuda_bf16.h>
#include <math.h>
#include <stdint.h>

#define NV 7
#define CIN 512
#define HH 64
#define WW 112
#define HWSZ (HH*WW)
#define DM 128
#define PP 36864
#define OC 64
#define BNEPS 1e-5f
#define PR0 512
#define PROWS 81024

__device__ __nv_bfloat16 g_feat[NV * HWSZ * DM];
__device__ float g_fused[PP * DM];
__device__ __nv_bfloat16 g_h2p[(size_t)PROWS * 128];
__device__ float g_h3[PP * OC];
__device__ __nv_bfloat16 g_wt[125 * OC * DM];   // [tap][o][c], bf16

__device__ __forceinline__ float to_tf32(float f) {
    uint32_t u; asm("cvt.rna.tf32.f32 %0, %1;" : "=r"(u) : "f"(f));
    return __uint_as_float(u);
}
__device__ __forceinline__ uint32_t smem_u32(const void* p) {
    uint32_t a;
    asm("{ .reg .u64 t; cvta.to.shared.u64 t, %1; cvt.u32.u64 %0, t; }" : "=r"(a) : "l"(p));
    return a;
}
__device__ __forceinline__ void cp16(uint32_t dst, const void* src) {
    asm volatile("cp.async.cg.shared.global [%0], [%1], 16;" :: "r"(dst), "l"(src));
}
__device__ __forceinline__ void mma8(float* d, const uint32_t* a, const uint32_t* b) {
    asm volatile(
        "mma.sync.aligned.m16n8k8.row.col.f32.tf32.tf32.f32 "
        "{%0,%1,%2,%3},{%4,%5,%6,%7},{%8,%9},{%0,%1,%2,%3};"
        : "+f"(d[0]), "+f"(d[1]), "+f"(d[2]), "+f"(d[3])
        : "r"(a[0]), "r"(a[1]), "r"(a[2]), "r"(a[3]), "r"(b[0]), "r"(b[1]));
}
__device__ __forceinline__ void mma16(float* d, const uint32_t* a, const uint32_t* b) {
    asm volatile(
        "mma.sync.aligned.m16n8k16.row.col.f32.bf16.bf16.f32 "
        "{%0,%1,%2,%3},{%4,%5,%6,%7},{%8,%9},{%0,%1,%2,%3};"
        : "+f"(d[0]), "+f"(d[1]), "+f"(d[2]), "+f"(d[3])
        : "r"(a[0]), "r"(a[1]), "r"(a[2]), "r"(a[3]), "r"(b[0]), "r"(b[1]));
}

// ---------- zero halo of padded volume (interior overwritten by k3 every launch) ----------
__global__ void k_zero() {
    size_t i = (size_t)blockIdx.x * 256 + threadIdx.x;
    if (i >= (size_t)PROWS * 16) return;
    int r = (int)(i >> 4);
    int pr = r - PR0;
    if (pr >= 0 && pr < 80000) {
        int zp = pr / 10000, rem = pr % 10000, yp = rem / 100, xp = rem % 100;
        if (zp >= 2 && zp < 6 && yp >= 2 && yp < 98 && xp >= 2 && xp < 98) return;
    }
    ((uint4*)g_h2p)[i] = make_uint4(0u, 0u, 0u, 0u);
}
// ---------- weight prep ----------
__global__ void k_wt(const float* __restrict__ w3b) {
    int idx = blockIdx.x * 256 + threadIdx.x;
    if (idx >= 125 * 8192) return;
    int t = idx >> 13, o = (idx >> 7) & 63, c = idx & 127;
    g_wt[idx] = __float2bfloat16_rn(w3b[(size_t)(o * 128 + c) * 125 + t]);
}

// ---------- k1: projection GEMM, cp.async 2-stage pipeline, tf32 mma (raw fp32 feed) ----------
// dyn smem: A[2][32][136]f @0, B[2][128][36]f @8704 floats; total 17920 f = 71680 B
#define K1_A_F 4352
#define K1_B_F 4608
#define SMEM_K1 ((2 * K1_A_F + 2 * K1_B_F) * 4)
__global__ __launch_bounds__(256) void k1_mma(
    const float* __restrict__ img, const float* __restrict__ wproj, const float* __restrict__ bproj,
    const float* __restrict__ g1, const float* __restrict__ bb1,
    const float* __restrict__ m1, const float* __restrict__ v1)
{
    extern __shared__ __align__(16) float s1[];
    float* sAb = s1;                    // [2][32][136]
    float* sBb = s1 + 2 * K1_A_F;       // [2][128][36]
    const uint32_t sAu = smem_u32(sAb);
    const uint32_t sBu = smem_u32(sBb);

    const int tid = threadIdx.x;
    const int lane = tid & 31, wid = tid >> 5;
    const int gq = lane >> 2, tq = lane & 3;
    const int wm = wid >> 1, wn = wid & 1;
    const int m0 = blockIdx.x * 128;
    const int n = m0 / HWSZ, hw0 = m0 % HWSZ;
    const float* ibase = img + (size_t)n * CIN * HWSZ + hw0;

    float acc[2][8][4];
    #pragma unroll
    for (int mt = 0; mt < 2; mt++)
        #pragma unroll
        for (int nt = 0; nt < 8; nt++)
            #pragma unroll
            for (int q = 0; q < 4; q++) acc[mt][nt][q] = 0.f;

    // issue tile 0
    {
        const float* asrc = ibase;
        #pragma unroll
        for (int i = tid; i < 1024; i += 256)
            cp16(sAu + (uint32_t)((i >> 5) * 136 + (i & 31) * 4) * 4, asrc + (size_t)(i >> 5) * HWSZ + (i & 31) * 4);
        #pragma unroll
        for (int i = tid; i < 1024; i += 256)
            cp16(sBu + (uint32_t)((i >> 3) * 36 + (i & 7) * 4) * 4, wproj + (size_t)(i >> 3) * CIN + (i & 7) * 4);
        asm volatile("cp.async.commit_group;" ::: "memory");
    }

    for (int t = 0; t < 16; t++) {
        const int buf = t & 1;
        if (t < 15) {
            const int k1 = (t + 1) * 32;
            const int nb = (t + 1) & 1;
            const float* asrc = ibase + (size_t)k1 * HWSZ;
            #pragma unroll
            for (int i = tid; i < 1024; i += 256)
                cp16(sAu + (uint32_t)(nb * K1_A_F + (i >> 5) * 136 + (i & 31) * 4) * 4,
                     asrc + (size_t)(i >> 5) * HWSZ + (i & 31) * 4);
            #pragma unroll
            for (int i = tid; i < 1024; i += 256)
                cp16(sBu + (uint32_t)(nb * K1_B_F + (i >> 3) * 36 + (i & 7) * 4) * 4,
                     wproj + (size_t)(i >> 3) * CIN + k1 + (i & 7) * 4);
            asm volatile("cp.async.commit_group;" ::: "memory");
            asm volatile("cp.async.wait_group 1;" ::: "memory");
        } else {
            asm volatile("cp.async.wait_group 0;" ::: "memory");
        }
        __syncthreads();
        const float* sA = sAb + buf * K1_A_F;   // [32][136]
        const float* sB = sBb + buf * K1_B_F;   // [128][36]
        #pragma unroll
        for (int ks = 0; ks < 4; ks++) {
            const int k = ks * 8;
            uint32_t a[2][4], b[8][2];
            #pragma unroll
            for (int mt = 0; mt < 2; mt++) {
                int row = wm * 32 + mt * 16 + gq;
                a[mt][0] = __float_as_uint(sA[(k + tq) * 136 + row]);
                a[mt][1] = __float_as_uint(sA[(k + tq) * 136 + row + 8]);
                a[mt][2] = __float_as_uint(sA[(k + tq + 4) * 136 + row]);
                a[mt][3] = __float_as_uint(sA[(k + tq + 4) * 136 + row + 8]);
            }
            #pragma unroll
            for (int nt = 0; nt < 8; nt++) {
                int dc = wn * 64 + nt * 8 + gq;
                b[nt][0] = __float_as_uint(sB[dc * 36 + k + tq]);
                b[nt][1] = __float_as_uint(sB[dc * 36 + k + tq + 4]);
            }
            #pragma unroll
            for (int mt = 0; mt < 2; mt++)
                #pragma unroll
                for (int nt = 0; nt < 8; nt++)
                    mma8(acc[mt][nt], a[mt], b[nt]);
        }
        __syncthreads();
    }
    float scv[8][2], shv[8][2];
    #pragma unroll
    for (int nt = 0; nt < 8; nt++) {
        #pragma unroll
        for (int j = 0; j < 2; j++) {
            int d = wn * 64 + nt * 8 + 2 * tq + j;
            float s = g1[d] * rsqrtf(v1[d] + BNEPS);
            scv[nt][j] = s;
            shv[nt][j] = (bproj[d] - m1[d]) * s + bb1[d];
        }
    }
    #pragma unroll
    for (int mt = 0; mt < 2; mt++) {
        #pragma unroll
        for (int h = 0; h < 2; h++) {
            int m = m0 + wm * 32 + mt * 16 + gq + h * 8;
            __nv_bfloat16* dst = g_feat + (size_t)m * DM + wn * 64 + 2 * tq;
            #pragma unroll
            for (int nt = 0; nt < 8; nt++) {
                float vx = fmaxf(acc[mt][nt][h * 2 + 0] * scv[nt][0] + shv[nt][0], 0.f);
                float vy = fmaxf(acc[mt][nt][h * 2 + 1] * scv[nt][1] + shv[nt][1], 0.f);
                *(__nv_bfloat162*)(dst + nt * 8) = __floats2bfloat162_rn(vx, vy);
            }
        }
    }
}

// ---------- k2: gather (bf16) + masked softmax fusion ----------
__global__ __launch_bounds__(128) void k2_fuse(
    const int* __restrict__ xi, const int* __restrict__ yi, const int* __restrict__ valid)
{
    __shared__ int slin[NV];
    const int p = blockIdx.x, d = threadIdx.x;
    if (d < NV) {
        int v = valid[d * PP + p];
        slin[d] = v ? (yi[d * PP + p] * WW + xi[d * PP + p]) : -1;
    }
    __syncthreads();
    float vv[NV];
    #pragma unroll
    for (int n = 0; n < NV; n++) {
        int lin = slin[n];
        float val = 0.f;
        if (lin >= 0)
            val = __bfloat162float(g_feat[((size_t)(n * HWSZ + lin)) * DM + d]);
        vv[n] = val;
    }
    float mx = vv[0];
    #pragma unroll
    for (int n = 1; n < NV; n++) mx = fmaxf(mx, vv[n]);
    float s = 0.f, ws = 0.f;
    #pragma unroll
    for (int n = 0; n < NV; n++) { float e = __expf(vv[n] - mx); s += e; ws += e * vv[n]; }
    g_fused[(size_t)p * DM + d] = ws / s;
}

// ---------- k3: 1x1 GEMM via mma.sync tf32 + BN2 + ReLU -> padded bf16 volume ----------
__global__ __launch_bounds__(256) void k3_mma(
    const float* __restrict__ w3a, const float* __restrict__ b3a,
    const float* __restrict__ g2, const float* __restrict__ bb2,
    const float* __restrict__ m2, const float* __restrict__ v2)
{
    __shared__ float sA[128][36];
    __shared__ float sB[128][36];
    const int tid = threadIdx.x;
    const int lane = tid & 31, wid = tid >> 5;
    const int gq = lane >> 2, tq = lane & 3;
    const int wm = wid >> 1, wn = wid & 1;
    const int m0 = blockIdx.x * 128;

    float acc[2][8][4];
    #pragma unroll
    for (int mt = 0; mt < 2; mt++)
        #pragma unroll
        for (int nt = 0; nt < 8; nt++)
            #pragma unroll
            for (int q = 0; q < 4; q++) acc[mt][nt][q] = 0.f;

    for (int k0 = 0; k0 < DM; k0 += 32) {
        __syncthreads();
        #pragma unroll 4
        for (int i = tid; i < 4096; i += 256) {
            int mm = i >> 5, kk = i & 31;
            sA[mm][kk] = g_fused[(size_t)(m0 + mm) * DM + k0 + kk];
            sB[mm][kk] = w3a[(size_t)mm * DM + k0 + kk];
        }
        __syncthreads();
        #pragma unroll
        for (int ks = 0; ks < 4; ks++) {
            const int k = ks * 8;
            uint32_t a[2][4], b[8][2];
            #pragma unroll
            for (int mt = 0; mt < 2; mt++) {
                const float* p = &sA[wm * 32 + mt * 16 + gq][k + tq];
                a[mt][0] = __float_as_uint(p[0]);
                a[mt][1] = __float_as_uint(p[8 * 36]);
                a[mt][2] = __float_as_uint(p[4]);
                a[mt][3] = __float_as_uint(p[8 * 36 + 4]);
            }
            #pragma unroll
            for (int nt = 0; nt < 8; nt++) {
                const float* p = &sB[wn * 64 + nt * 8 + gq][k + tq];
                b[nt][0] = __float_as_uint(p[0]);
                b[nt][1] = __float_as_uint(p[4]);
            }
            #pragma unroll
            for (int mt = 0; mt < 2; mt++)
                #pragma unroll
                for (int nt = 0; nt < 8; nt++)
                    mma8(acc[mt][nt], a[mt], b[nt]);
        }
    }
    float scv[8][2], shv[8][2];
    #pragma unroll
    for (int nt = 0; nt < 8; nt++) {
        #pragma unroll
        for (int j = 0; j < 2; j++) {
            int d = wn * 64 + nt * 8 + 2 * tq + j;
            float s = g2[d] * rsqrtf(v2[d] + BNEPS);
            scv[nt][j] = s;
            shv[nt][j] = (b3a[d] - m2[d]) * s + bb2[d];
        }
    }
    #pragma unroll
    for (int mt = 0; mt < 2; mt++) {
        #pragma unroll
        for (int h = 0; h < 2; h++) {
            int m = m0 + wm * 32 + mt * 16 + gq + h * 8;
            int z = m / 9216, rem = m % 9216, y = rem / 96, x = rem % 96;
            size_t pm = (size_t)(z + 2) * 10000 + (y + 2) * 100 + (x + 2) + PR0;
            __nv_bfloat16* dst = g_h2p + pm * 128 + wn * 64 + 2 * tq;
            #pragma unroll
            for (int nt = 0; nt < 8; nt++) {
                float vx = fmaxf(acc[mt][nt][h * 2 + 0] * scv[nt][0] + shv[nt][0], 0.f);
                float vy = fmaxf(acc[mt][nt][h * 2 + 1] * scv[nt][1] + shv[nt][1], 0.f);
                *(__nv_bfloat162*)(dst + nt * 8) = __floats2bfloat162_rn(vx, vy);
            }
        }
    }
}

// ---------- k4: 5x5x5 conv via mma.sync bf16, cp.async double-buffered B ----------
#define SA_ST 136
#define SB_ST 136
#define SA_BYTES (132 * SA_ST * 2)      // 35904
#define SB_BYTES (64 * SB_ST * 2)       // 17408
#define SMEM_K4 (SA_BYTES + 2 * SB_BYTES)   // 70720
__global__ __launch_bounds__(128, 3) void k4_mma(
    const float* __restrict__ b3b, const float* __restrict__ g3,
    const float* __restrict__ bb3, const float* __restrict__ m3, const float* __restrict__ v3)
{
    extern __shared__ __align__(16) char smem[];
    __nv_bfloat16* sA = (__nv_bfloat16*)smem;
    const uint32_t sbase = smem_u32(smem);
    const uint32_t sAu = sbase;
    const uint32_t sBu0 = sbase + SA_BYTES;

    const int tid = threadIdx.x;
    const int lane = tid & 31, wm = tid >> 5;
    const int gq = lane >> 2, tq = lane & 3;
    const int m0 = 20000 + blockIdx.x * 128;

    float acc[2][8][4];
    #pragma unroll
    for (int mt = 0; mt < 2; mt++)
        #pragma unroll
        for (int nt = 0; nt < 8; nt++)
            #pragma unroll
            for (int q = 0; q < 4; q++) acc[mt][nt][q] = 0.f;

    for (int kd = 0; kd < 5; kd++) {
        for (int kh = 0; kh < 5; kh++) {
            const int arow0 = m0 + (kd - 2) * 10000 + (kh - 2) * 100 - 2;
            if (arow0 >= 60000 || arow0 + 131 < 20000) continue;
            __syncthreads();
            {
                const uint4* src = (const uint4*)(g_h2p) + ((size_t)arow0 + PR0) * 16;
                #pragma unroll 4
                for (int i = tid; i < 132 * 16; i += 128)
                    cp16(sAu + (uint32_t)((i >> 4) * SA_ST * 2 + (i & 15) * 16), src + i);
            }
            {
                const int tap0 = (kd * 5 + kh) * 5;
                const uint4* src = (const uint4*)(g_wt) + (size_t)tap0 * 1024;
                #pragma unroll 4
                for (int i = tid; i < 1024; i += 128)
                    cp16(sBu0 + (uint32_t)((i >> 4) * SB_ST * 2 + (i & 15) * 16), src + i);
            }
            asm volatile("cp.async.commit_group;" ::: "memory");
            asm volatile("cp.async.wait_group 0;" ::: "memory");
            __syncthreads();
            for (int kw = 0; kw < 5; kw++) {
                if (kw < 4) {
                    const int tap = (kd * 5 + kh) * 5 + kw + 1;
                    const uint4* src = (const uint4*)(g_wt) + (size_t)tap * 1024;
                    const uint32_t nxtB = sBu0 + (uint32_t)((kw + 1) & 1) * SB_BYTES;
                    #pragma unroll 4
                    for (int i = tid; i < 1024; i += 128)
                        cp16(nxtB + (uint32_t)((i >> 4) * SB_ST * 2 + (i & 15) * 16), src + i);
                    asm volatile("cp.async.commit_group;" ::: "memory");
                }
                const __nv_bfloat16* sBk = (const __nv_bfloat16*)smem + (SA_BYTES / 2) + (kw & 1) * (SB_BYTES / 2);
                #pragma unroll 2
                for (int ks = 0; ks < 8; ks++) {
                    const int k0 = ks * 16;
                    uint32_t a[2][4], b[8][2];
                    #pragma unroll
                    for (int mt = 0; mt < 2; mt++) {
                        const __nv_bfloat16* p = sA + (size_t)(wm * 32 + mt * 16 + gq + kw) * SA_ST + k0 + 2 * tq;
                        a[mt][0] = *(const uint32_t*)(p);
                        a[mt][1] = *(const uint32_t*)(p + 8 * SA_ST);
                        a[mt][2] = *(const uint32_t*)(p + 8);
                        a[mt][3] = *(const uint32_t*)(p + 8 * SA_ST + 8);
                    }
                    #pragma unroll
                    for (int nt = 0; nt < 8; nt++) {
                        const __nv_bfloat16* p = sBk + (size_t)(nt * 8 + gq) * SB_ST + k0 + 2 * tq;
                        b[nt][0] = *(const uint32_t*)(p);
                        b[nt][1] = *(const uint32_t*)(p + 8);
                    }
                    #pragma unroll
                    for (int mt = 0; mt < 2; mt++)
                        #pragma unroll
                        for (int nt = 0; nt < 8; nt++)
                            mma16(acc[mt][nt], a[mt], b[nt]);
                }
                if (kw < 4) {
                    asm volatile("cp.async.wait_group 0;" ::: "memory");
                    __syncthreads();
                }
            }
        }
    }

    float scv[8][2], shv[8][2];
    #pragma unroll
    for (int nt = 0; nt < 8; nt++) {
        #pragma unroll
        for (int j = 0; j < 2; j++) {
            int oc = nt * 8 + 2 * tq + j;
            float s = g3[oc] * rsqrtf(v3[oc] + BNEPS);
            scv[nt][j] = s;
            shv[nt][j] = (b3b[oc] - m3[oc]) * s + bb3[oc];
        }
    }
    #pragma unroll
    for (int mt = 0; mt < 2; mt++) {
        #pragma unroll
        for (int h = 0; h < 2; h++) {
            int pm = m0 + wm * 32 + mt * 16 + gq + h * 8;
            int zp = pm / 10000, r2 = pm % 10000, yp = r2 / 100, xp = r2 % 100;
            if (zp >= 2 && zp < 6 && yp >= 2 && yp < 98 && xp >= 2 && xp < 98) {
                int vox = (zp - 2) * 9216 + (yp - 2) * 96 + (xp - 2);
                float* dst = g_h3 + (size_t)vox * 64 + 2 * tq;
                #pragma unroll
                for (int nt = 0; nt < 8; nt++) {
                    float2 v;
                    v.x = fmaxf(acc[mt][nt][h * 2 + 0] * scv[nt][0] + shv[nt][0], 0.f);
                    v.y = fmaxf(acc[mt][nt][h * 2 + 1] * scv[nt][1] + shv[nt][1], 0.f);
                    *(float2*)(dst + nt * 8) = v;
                }
            }
        }
    }
}

// ---------- k5: 1x1 head (64->4) + sigmoid, thread-per-voxel ----------
__global__ __launch_bounds__(256) void k5_head(
    const float* __restrict__ w3c, const float* __restrict__ b3c, float* __restrict__ out)
{
    __shared__ float sw[256];
    const int tid = threadIdx.x;
    sw[tid] = w3c[tid];
    __syncthreads();
    const int vox = blockIdx.x * 256 + tid;
    const float4* h = (const float4*)(g_h3 + (size_t)vox * OC);
    float r0 = b3c[0], r1 = b3c[1], r2 = b3c[2], r3 = b3c[3];
    #pragma unroll
    for (int q = 0; q < 16; q++) {
        float4 v = h[q];
        const float* w0 = sw + q * 4;
        r0 += v.x * w0[0]   + v.y * w0[1]   + v.z * w0[2]   + v.w * w0[3];
        r1 += v.x * w0[64]  + v.y * w0[65]  + v.z * w0[66]  + v.w * w0[67];
        r2 += v.x * w0[128] + v.y * w0[129] + v.z * w0[130] + v.w * w0[131];
        r3 += v.x * w0[192] + v.y * w0[193] + v.z * w0[194] + v.w * w0[195];
    }
    out[0 * PP + vox] = 1.f / (1.f + __expf(-r0));
    out[1 * PP + vox] = 1.f / (1.f + __expf(-r1));
    out[2 * PP + vox] = 1.f / (1.f + __expf(-r2));
    out[3 * PP + vox] = 1.f / (1.f + __expf(-r3));
}

extern "C" void kernel_launch(void* const* d_in, const int* in_sizes, int n_in,
                              void* d_out, int out_size)
{
    const float* img = (const float*)d_in[0];
    const int* xi = (const int*)d_in[1];
    const int* yi = (const int*)d_in[2];
    const int* valid = (const int*)d_in[3];
    const float* wproj = (const float*)d_in[4];
    const float* bproj = (const float*)d_in[5];
    const float* bn1g = (const float*)d_in[6];
    const float* bn1b = (const float*)d_in[7];
    const float* bn1m = (const float*)d_in[8];
    const float* bn1v = (const float*)d_in[9];
    const float* w3a = (const float*)d_in[10];
    const float* b3a = (const float*)d_in[11];
    const float* bn2g = (const float*)d_in[12];
    const float* bn2b = (const float*)d_in[13];
    const float* bn2m = (const float*)d_in[14];
    const float* bn2v = (const float*)d_in[15];
    const float* w3b = (const float*)d_in[16];
    const float* b3b = (const float*)d_in[17];
    const float* bn3g = (const float*)d_in[18];
    const float* bn3b = (const float*)d_in[19];
    const float* bn3m = (const float*)d_in[20];
    const float* bn3v = (const float*)d_in[21];
    const float* w3c = (const float*)d_in[22];
    const float* b3c = (const float*)d_in[23];
    float* out = (float*)d_out;

    cudaFuncSetAttribute(k1_mma, cudaFuncAttributeMaxDynamicSharedMemorySize, SMEM_K1);
    cudaFuncSetAttribute(k4_mma, cudaFuncAttributeMaxDynamicSharedMemorySize, SMEM_K4);
    k_zero<<<(PROWS * 16 + 255) / 256, 256>>>();
    k_wt<<<(125 * 8192 + 255) / 256, 256>>>(w3b);
    k1_mma<<<(NV * HWSZ) / 128, 256, SMEM_K1>>>(img, wproj, bproj, bn1g, bn1b, bn1m, bn1v);
    k2_fuse<<<PP, 128>>>(xi, yi, valid);
    k3_mma<<<PP / 128, 256>>>(w3a, b3a, bn2g, bn2b, bn2m, bn2v);
    k4_mma<<<313, 128, SMEM_K4>>>(b3b, bn3g, bn3b, bn3m, bn3v);
    k5_head<<<PP / 256, 256>>>(w3c, b3c, out);
}

// round 16
// speedup vs baseline: 6.8037x; 1.0686x over previous
#include <cuda_runtime.h>
#include <cuda_bf16.h>
#include <math.h>
#include <stdint.h>

#define NV 7
#define CIN 512
#define HH 64
#define WW 112
#define HWSZ (HH*WW)
#define DM 128
#define PP 36864
#define OC 64
#define BNEPS 1e-5f
#define PR0 512
#define PROWS 81024

__device__ __nv_bfloat16 g_feat[NV * HWSZ * DM];
__device__ float g_fused[PP * DM];
__device__ __nv_bfloat16 g_h2p[(size_t)PROWS * 128];
__device__ float g_h3[PP * OC];
__device__ __nv_bfloat16 g_wt[125 * OC * DM];   // [tap][o][c], bf16

__device__ __forceinline__ uint32_t smem_u32(const void* p) {
    uint32_t a;
    asm("{ .reg .u64 t; cvta.to.shared.u64 t, %1; cvt.u32.u64 %0, t; }" : "=r"(a) : "l"(p));
    return a;
}
__device__ __forceinline__ void cp16(uint32_t dst, const void* src) {
    asm volatile("cp.async.cg.shared.global [%0], [%1], 16;" :: "r"(dst), "l"(src));
}
__device__ __forceinline__ void mma8(float* d, const uint32_t* a, const uint32_t* b) {
    asm volatile(
        "mma.sync.aligned.m16n8k8.row.col.f32.tf32.tf32.f32 "
        "{%0,%1,%2,%3},{%4,%5,%6,%7},{%8,%9},{%0,%1,%2,%3};"
        : "+f"(d[0]), "+f"(d[1]), "+f"(d[2]), "+f"(d[3])
        : "r"(a[0]), "r"(a[1]), "r"(a[2]), "r"(a[3]), "r"(b[0]), "r"(b[1]));
}
__device__ __forceinline__ void mma16(float* d, const uint32_t* a, const uint32_t* b) {
    asm volatile(
        "mma.sync.aligned.m16n8k16.row.col.f32.bf16.bf16.f32 "
        "{%0,%1,%2,%3},{%4,%5,%6,%7},{%8,%9},{%0,%1,%2,%3};"
        : "+f"(d[0]), "+f"(d[1]), "+f"(d[2]), "+f"(d[3])
        : "r"(a[0]), "r"(a[1]), "r"(a[2]), "r"(a[3]), "r"(b[0]), "r"(b[1]));
}
#define LDSM4(r0, r1, r2, r3, addr) \
    asm volatile("ldmatrix.sync.aligned.m8n8.x4.shared.b16 {%0,%1,%2,%3}, [%4];" \
        : "=r"(r0), "=r"(r1), "=r"(r2), "=r"(r3) : "r"(addr))

// ---------- zero halo of padded volume (interior overwritten by k3 every launch) ----------
__global__ void k_zero() {
    size_t i = (size_t)blockIdx.x * 256 + threadIdx.x;
    if (i >= (size_t)PROWS * 16) return;
    int r = (int)(i >> 4);
    int pr = r - PR0;
    if (pr >= 0 && pr < 80000) {
        int zp = pr / 10000, rem = pr % 10000, yp = rem / 100, xp = rem % 100;
        if (zp >= 2 && zp < 6 && yp >= 2 && yp < 98 && xp >= 2 && xp < 98) return;
    }
    ((uint4*)g_h2p)[i] = make_uint4(0u, 0u, 0u, 0u);
}
// ---------- weight prep ----------
__global__ void k_wt(const float* __restrict__ w3b) {
    int idx = blockIdx.x * 256 + threadIdx.x;
    if (idx >= 125 * 8192) return;
    int t = idx >> 13, o = (idx >> 7) & 63, c = idx & 127;
    g_wt[idx] = __float2bfloat16_rn(w3b[(size_t)(o * 128 + c) * 125 + t]);
}

// ---------- k1: projection GEMM, cp.async 2-stage pipeline, tf32 mma (raw fp32 feed) ----------
#define K1_A_F 4352
#define K1_B_F 4608
#define SMEM_K1 ((2 * K1_A_F + 2 * K1_B_F) * 4)
__global__ __launch_bounds__(256) void k1_mma(
    const float* __restrict__ img, const float* __restrict__ wproj, const float* __restrict__ bproj,
    const float* __restrict__ g1, const float* __restrict__ bb1,
    const float* __restrict__ m1, const float* __restrict__ v1)
{
    extern __shared__ __align__(16) float s1[];
    float* sAb = s1;
    float* sBb = s1 + 2 * K1_A_F;
    const uint32_t sAu = smem_u32(sAb);
    const uint32_t sBu = smem_u32(sBb);

    const int tid = threadIdx.x;
    const int lane = tid & 31, wid = tid >> 5;
    const int gq = lane >> 2, tq = lane & 3;
    const int wm = wid >> 1, wn = wid & 1;
    const int m0 = blockIdx.x * 128;
    const int n = m0 / HWSZ, hw0 = m0 % HWSZ;
    const float* ibase = img + (size_t)n * CIN * HWSZ + hw0;

    float acc[2][8][4];
    #pragma unroll
    for (int mt = 0; mt < 2; mt++)
        #pragma unroll
        for (int nt = 0; nt < 8; nt++)
            #pragma unroll
            for (int q = 0; q < 4; q++) acc[mt][nt][q] = 0.f;

    {
        const float* asrc = ibase;
        #pragma unroll
        for (int i = tid; i < 1024; i += 256)
            cp16(sAu + (uint32_t)((i >> 5) * 136 + (i & 31) * 4) * 4, asrc + (size_t)(i >> 5) * HWSZ + (i & 31) * 4);
        #pragma unroll
        for (int i = tid; i < 1024; i += 256)
            cp16(sBu + (uint32_t)((i >> 3) * 36 + (i & 7) * 4) * 4, wproj + (size_t)(i >> 3) * CIN + (i & 7) * 4);
        asm volatile("cp.async.commit_group;" ::: "memory");
    }

    for (int t = 0; t < 16; t++) {
        const int buf = t & 1;
        if (t < 15) {
            const int k1 = (t + 1) * 32;
            const int nb = (t + 1) & 1;
            const float* asrc = ibase + (size_t)k1 * HWSZ;
            #pragma unroll
            for (int i = tid; i < 1024; i += 256)
                cp16(sAu + (uint32_t)(nb * K1_A_F + (i >> 5) * 136 + (i & 31) * 4) * 4,
                     asrc + (size_t)(i >> 5) * HWSZ + (i & 31) * 4);
            #pragma unroll
            for (int i = tid; i < 1024; i += 256)
                cp16(sBu + (uint32_t)(nb * K1_B_F + (i >> 3) * 36 + (i & 7) * 4) * 4,
                     wproj + (size_t)(i >> 3) * CIN + k1 + (i & 7) * 4);
            asm volatile("cp.async.commit_group;" ::: "memory");
            asm volatile("cp.async.wait_group 1;" ::: "memory");
        } else {
            asm volatile("cp.async.wait_group 0;" ::: "memory");
        }
        __syncthreads();
        const float* sA = sAb + buf * K1_A_F;
        const float* sB = sBb + buf * K1_B_F;
        #pragma unroll
        for (int ks = 0; ks < 4; ks++) {
            const int k = ks * 8;
            uint32_t a[2][4], b[8][2];
            #pragma unroll
            for (int mt = 0; mt < 2; mt++) {
                int row = wm * 32 + mt * 16 + gq;
                a[mt][0] = __float_as_uint(sA[(k + tq) * 136 + row]);
                a[mt][1] = __float_as_uint(sA[(k + tq) * 136 + row + 8]);
                a[mt][2] = __float_as_uint(sA[(k + tq + 4) * 136 + row]);
                a[mt][3] = __float_as_uint(sA[(k + tq + 4) * 136 + row + 8]);
            }
            #pragma unroll
            for (int nt = 0; nt < 8; nt++) {
                int dc = wn * 64 + nt * 8 + gq;
                b[nt][0] = __float_as_uint(sB[dc * 36 + k + tq]);
                b[nt][1] = __float_as_uint(sB[dc * 36 + k + tq + 4]);
            }
            #pragma unroll
            for (int mt = 0; mt < 2; mt++)
                #pragma unroll
                for (int nt = 0; nt < 8; nt++)
                    mma8(acc[mt][nt], a[mt], b[nt]);
        }
        __syncthreads();
    }
    float scv[8][2], shv[8][2];
    #pragma unroll
    for (int nt = 0; nt < 8; nt++) {
        #pragma unroll
        for (int j = 0; j < 2; j++) {
            int d = wn * 64 + nt * 8 + 2 * tq + j;
            float s = g1[d] * rsqrtf(v1[d] + BNEPS);
            scv[nt][j] = s;
            shv[nt][j] = (bproj[d] - m1[d]) * s + bb1[d];
        }
    }
    #pragma unroll
    for (int mt = 0; mt < 2; mt++) {
        #pragma unroll
        for (int h = 0; h < 2; h++) {
            int m = m0 + wm * 32 + mt * 16 + gq + h * 8;
            __nv_bfloat16* dst = g_feat + (size_t)m * DM + wn * 64 + 2 * tq;
            #pragma unroll
            for (int nt = 0; nt < 8; nt++) {
                float vx = fmaxf(acc[mt][nt][h * 2 + 0] * scv[nt][0] + shv[nt][0], 0.f);
                float vy = fmaxf(acc[mt][nt][h * 2 + 1] * scv[nt][1] + shv[nt][1], 0.f);
                *(__nv_bfloat162*)(dst + nt * 8) = __floats2bfloat162_rn(vx, vy);
            }
        }
    }
}

// ---------- k2: gather (bf16) + masked softmax fusion ----------
__global__ __launch_bounds__(128) void k2_fuse(
    const int* __restrict__ xi, const int* __restrict__ yi, const int* __restrict__ valid)
{
    __shared__ int slin[NV];
    const int p = blockIdx.x, d = threadIdx.x;
    if (d < NV) {
        int v = valid[d * PP + p];
        slin[d] = v ? (yi[d * PP + p] * WW + xi[d * PP + p]) : -1;
    }
    __syncthreads();
    float vv[NV];
    #pragma unroll
    for (int n = 0; n < NV; n++) {
        int lin = slin[n];
        float val = 0.f;
        if (lin >= 0)
            val = __bfloat162float(g_feat[((size_t)(n * HWSZ + lin)) * DM + d]);
        vv[n] = val;
    }
    float mx = vv[0];
    #pragma unroll
    for (int n = 1; n < NV; n++) mx = fmaxf(mx, vv[n]);
    float s = 0.f, ws = 0.f;
    #pragma unroll
    for (int n = 0; n < NV; n++) { float e = __expf(vv[n] - mx); s += e; ws += e * vv[n]; }
    g_fused[(size_t)p * DM + d] = ws / s;
}

// ---------- k3: 1x1 GEMM via mma.sync tf32 + BN2 + ReLU -> padded bf16 volume ----------
__global__ __launch_bounds__(256) void k3_mma(
    const float* __restrict__ w3a, const float* __restrict__ b3a,
    const float* __restrict__ g2, const float* __restrict__ bb2,
    const float* __restrict__ m2, const float* __restrict__ v2)
{
    __shared__ float sA[128][36];
    __shared__ float sB[128][36];
    const int tid = threadIdx.x;
    const int lane = tid & 31, wid = tid >> 5;
    const int gq = lane >> 2, tq = lane & 3;
    const int wm = wid >> 1, wn = wid & 1;
    const int m0 = blockIdx.x * 128;

    float acc[2][8][4];
    #pragma unroll
    for (int mt = 0; mt < 2; mt++)
        #pragma unroll
        for (int nt = 0; nt < 8; nt++)
            #pragma unroll
            for (int q = 0; q < 4; q++) acc[mt][nt][q] = 0.f;

    for (int k0 = 0; k0 < DM; k0 += 32) {
        __syncthreads();
        #pragma unroll 4
        for (int i = tid; i < 4096; i += 256) {
            int mm = i >> 5, kk = i & 31;
            sA[mm][kk] = g_fused[(size_t)(m0 + mm) * DM + k0 + kk];
            sB[mm][kk] = w3a[(size_t)mm * DM + k0 + kk];
        }
        __syncthreads();
        #pragma unroll
        for (int ks = 0; ks < 4; ks++) {
            const int k = ks * 8;
            uint32_t a[2][4], b[8][2];
            #pragma unroll
            for (int mt = 0; mt < 2; mt++) {
                const float* p = &sA[wm * 32 + mt * 16 + gq][k + tq];
                a[mt][0] = __float_as_uint(p[0]);
                a[mt][1] = __float_as_uint(p[8 * 36]);
                a[mt][2] = __float_as_uint(p[4]);
                a[mt][3] = __float_as_uint(p[8 * 36 + 4]);
            }
            #pragma unroll
            for (int nt = 0; nt < 8; nt++) {
                const float* p = &sB[wn * 64 + nt * 8 + gq][k + tq];
                b[nt][0] = __float_as_uint(p[0]);
                b[nt][1] = __float_as_uint(p[4]);
            }
            #pragma unroll
            for (int mt = 0; mt < 2; mt++)
                #pragma unroll
                for (int nt = 0; nt < 8; nt++)
                    mma8(acc[mt][nt], a[mt], b[nt]);
        }
    }
    float scv[8][2], shv[8][2];
    #pragma unroll
    for (int nt = 0; nt < 8; nt++) {
        #pragma unroll
        for (int j = 0; j < 2; j++) {
            int d = wn * 64 + nt * 8 + 2 * tq + j;
            float s = g2[d] * rsqrtf(v2[d] + BNEPS);
            scv[nt][j] = s;
            shv[nt][j] = (b3a[d] - m2[d]) * s + bb2[d];
        }
    }
    #pragma unroll
    for (int mt = 0; mt < 2; mt++) {
        #pragma unroll
        for (int h = 0; h < 2; h++) {
            int m = m0 + wm * 32 + mt * 16 + gq + h * 8;
            int z = m / 9216, rem = m % 9216, y = rem / 96, x = rem % 96;
            size_t pm = (size_t)(z + 2) * 10000 + (y + 2) * 100 + (x + 2) + PR0;
            __nv_bfloat16* dst = g_h2p + pm * 128 + wn * 64 + 2 * tq;
            #pragma unroll
            for (int nt = 0; nt < 8; nt++) {
                float vx = fmaxf(acc[mt][nt][h * 2 + 0] * scv[nt][0] + shv[nt][0], 0.f);
                float vy = fmaxf(acc[mt][nt][h * 2 + 1] * scv[nt][1] + shv[nt][1], 0.f);
                *(__nv_bfloat162*)(dst + nt * 8) = __floats2bfloat162_rn(vx, vy);
            }
        }
    }
}

// ---------- k4: 5x5x5 conv, mma.sync bf16, ldmatrix frags, cp.async dbuf B ----------
#define SA_ST 136
#define SB_ST 136
#define SA_BYTES (132 * SA_ST * 2)      // 35904
#define SB_BYTES (64 * SB_ST * 2)       // 17408
#define SMEM_K4 (SA_BYTES + 2 * SB_BYTES)   // 70720
__global__ __launch_bounds__(128, 3) void k4_mma(
    const float* __restrict__ b3b, const float* __restrict__ g3,
    const float* __restrict__ bb3, const float* __restrict__ m3, const float* __restrict__ v3)
{
    extern __shared__ __align__(16) char smem[];
    const uint32_t sbase = smem_u32(smem);
    const uint32_t sAu = sbase;
    const uint32_t sBu0 = sbase + SA_BYTES;

    const int tid = threadIdx.x;
    const int lane = tid & 31, wm = tid >> 5;
    const int gq = lane >> 2, tq = lane & 3;
    const int m0 = 20000 + blockIdx.x * 128;

    // ldmatrix per-lane address components
    const int a_row0 = wm * 32 + ((lane >> 3) & 1) * 8 + (lane & 7);  // + mt*16 + kw
    const uint32_t a_colb = (uint32_t)((lane >> 4) & 1) * 16;         // k-half (8 bf16)
    int b_row[4];
    #pragma unroll
    for (int j = 0; j < 4; j++)
        b_row[j] = 16 * j + (((lane >> 4) & 1) << 3) + (lane & 7);
    const uint32_t b_colb = (uint32_t)((lane >> 3) & 1) * 16;

    float acc[2][8][4];
    #pragma unroll
    for (int mt = 0; mt < 2; mt++)
        #pragma unroll
        for (int nt = 0; nt < 8; nt++)
            #pragma unroll
            for (int q = 0; q < 4; q++) acc[mt][nt][q] = 0.f;

    for (int kd = 0; kd < 5; kd++) {
        for (int kh = 0; kh < 5; kh++) {
            const int arow0 = m0 + (kd - 2) * 10000 + (kh - 2) * 100 - 2;
            if (arow0 >= 60000 || arow0 + 131 < 20000) continue;
            __syncthreads();
            {
                const uint4* src = (const uint4*)(g_h2p) + ((size_t)arow0 + PR0) * 16;
                #pragma unroll 4
                for (int i = tid; i < 132 * 16; i += 128)
                    cp16(sAu + (uint32_t)((i >> 4) * SA_ST * 2 + (i & 15) * 16), src + i);
            }
            {
                const int tap0 = (kd * 5 + kh) * 5;
                const uint4* src = (const uint4*)(g_wt) + (size_t)tap0 * 1024;
                #pragma unroll 4
                for (int i = tid; i < 1024; i += 128)
                    cp16(sBu0 + (uint32_t)((i >> 4) * SB_ST * 2 + (i & 15) * 16), src + i);
            }
            asm volatile("cp.async.commit_group;" ::: "memory");
            asm volatile("cp.async.wait_group 0;" ::: "memory");
            __syncthreads();
            for (int kw = 0; kw < 5; kw++) {
                if (kw < 4) {
                    const int tap = (kd * 5 + kh) * 5 + kw + 1;
                    const uint4* src = (const uint4*)(g_wt) + (size_t)tap * 1024;
                    const uint32_t nxtB = sBu0 + (uint32_t)((kw + 1) & 1) * SB_BYTES;
                    #pragma unroll 4
                    for (int i = tid; i < 1024; i += 128)
                        cp16(nxtB + (uint32_t)((i >> 4) * SB_ST * 2 + (i & 15) * 16), src + i);
                    asm volatile("cp.async.commit_group;" ::: "memory");
                }
                const uint32_t curBu = sBu0 + (uint32_t)(kw & 1) * SB_BYTES;
                const uint32_t aw0 = sAu + (uint32_t)(a_row0 + kw) * (SA_ST * 2) + a_colb;
                const uint32_t aw1 = aw0 + 16u * (SA_ST * 2);
                uint32_t bw[4];
                #pragma unroll
                for (int j = 0; j < 4; j++)
                    bw[j] = curBu + (uint32_t)b_row[j] * (SB_ST * 2) + b_colb;
                #pragma unroll 2
                for (int ks = 0; ks < 8; ks++) {
                    const uint32_t k0b = (uint32_t)ks * 32;
                    uint32_t a[2][4], b[8][2];
                    LDSM4(a[0][0], a[0][1], a[0][2], a[0][3], aw0 + k0b);
                    LDSM4(a[1][0], a[1][1], a[1][2], a[1][3], aw1 + k0b);
                    #pragma unroll
                    for (int j = 0; j < 4; j++) {
                        uint32_t r0, r1, r2, r3;
                        LDSM4(r0, r1, r2, r3, bw[j] + k0b);
                        b[2 * j][0] = r0; b[2 * j][1] = r1;
                        b[2 * j + 1][0] = r2; b[2 * j + 1][1] = r3;
                    }
                    #pragma unroll
                    for (int mt = 0; mt < 2; mt++)
                        #pragma unroll
                        for (int nt = 0; nt < 8; nt++)
                            mma16(acc[mt][nt], a[mt], b[nt]);
                }
                if (kw < 4) {
                    asm volatile("cp.async.wait_group 0;" ::: "memory");
                    __syncthreads();
                }
            }
        }
    }

    float scv[8][2], shv[8][2];
    #pragma unroll
    for (int nt = 0; nt < 8; nt++) {
        #pragma unroll
        for (int j = 0; j < 2; j++) {
            int oc = nt * 8 + 2 * tq + j;
            float s = g3[oc] * rsqrtf(v3[oc] + BNEPS);
            scv[nt][j] = s;
            shv[nt][j] = (b3b[oc] - m3[oc]) * s + bb3[oc];
        }
    }
    #pragma unroll
    for (int mt = 0; mt < 2; mt++) {
        #pragma unroll
        for (int h = 0; h < 2; h++) {
            int pm = m0 + wm * 32 + mt * 16 + gq + h * 8;
            int zp = pm / 10000, r2 = pm % 10000, yp = r2 / 100, xp = r2 % 100;
            if (zp >= 2 && zp < 6 && yp >= 2 && yp < 98 && xp >= 2 && xp < 98) {
                int vox = (zp - 2) * 9216 + (yp - 2) * 96 + (xp - 2);
                float* dst = g_h3 + (size_t)vox * 64 + 2 * tq;
                #pragma unroll
                for (int nt = 0; nt < 8; nt++) {
                    float2 v;
                    v.x = fmaxf(acc[mt][nt][h * 2 + 0] * scv[nt][0] + shv[nt][0], 0.f);
                    v.y = fmaxf(acc[mt][nt][h * 2 + 1] * scv[nt][1] + shv[nt][1], 0.f);
                    *(float2*)(dst + nt * 8) = v;
                }
            }
        }
    }
}

// ---------- k5: 1x1 head (64->4) + sigmoid, thread-per-voxel ----------
__global__ __launch_bounds__(256) void k5_head(
    const float* __restrict__ w3c, const float* __restrict__ b3c, float* __restrict__ out)
{
    __shared__ float sw[256];
    const int tid = threadIdx.x;
    sw[tid] = w3c[tid];
    __syncthreads();
    const int vox = blockIdx.x * 256 + tid;
    const float4* h = (const float4*)(g_h3 + (size_t)vox * OC);
    float r0 = b3c[0], r1 = b3c[1], r2 = b3c[2], r3 = b3c[3];
    #pragma unroll
    for (int q = 0; q < 16; q++) {
        float4 v = h[q];
        const float* w0 = sw + q * 4;
        r0 += v.x * w0[0]   + v.y * w0[1]   + v.z * w0[2]   + v.w * w0[3];
        r1 += v.x * w0[64]  + v.y * w0[65]  + v.z * w0[66]  + v.w * w0[67];
        r2 += v.x * w0[128] + v.y * w0[129] + v.z * w0[130] + v.w * w0[131];
        r3 += v.x * w0[192] + v.y * w0[193] + v.z * w0[194] + v.w * w0[195];
    }
    out[0 * PP + vox] = 1.f / (1.f + __expf(-r0));
    out[1 * PP + vox] = 1.f / (1.f + __expf(-r1));
    out[2 * PP + vox] = 1.f / (1.f + __expf(-r2));
    out[3 * PP + vox] = 1.f / (1.f + __expf(-r3));
}

extern "C" void kernel_launch(void* const* d_in, const int* in_sizes, int n_in,
                              void* d_out, int out_size)
{
    const float* img = (const float*)d_in[0];
    const int* xi = (const int*)d_in[1];
    const int* yi = (const int*)d_in[2];
    const int* valid = (const int*)d_in[3];
    const float* wproj = (const float*)d_in[4];
    const float* bproj = (const float*)d_in[5];
    const float* bn1g = (const float*)d_in[6];
    const float* bn1b = (const float*)d_in[7];
    const float* bn1m = (const float*)d_in[8];
    const float* bn1v = (const float*)d_in[9];
    const float* w3a = (const float*)d_in[10];
    const float* b3a = (const float*)d_in[11];
    const float* bn2g = (const float*)d_in[12];
    const float* bn2b = (const float*)d_in[13];
    const float* bn2m = (const float*)d_in[14];
    const float* bn2v = (const float*)d_in[15];
    const float* w3b = (const float*)d_in[16];
    const float* b3b = (const float*)d_in[17];
    const float* bn3g = (const float*)d_in[18];
    const float* bn3b = (const float*)d_in[19];
    const float* bn3m = (const float*)d_in[20];
    const float* bn3v = (const float*)d_in[21];
    const float* w3c = (const float*)d_in[22];
    const float* b3c = (const float*)d_in[23];
    float* out = (float*)d_out;

    cudaFuncSetAttribute(k1_mma, cudaFuncAttributeMaxDynamicSharedMemorySize, SMEM_K1);
    cudaFuncSetAttribute(k4_mma, cudaFuncAttributeMaxDynamicSharedMemorySize, SMEM_K4);
    k_zero<<<(PROWS * 16 + 255) / 256, 256>>>();
    k_wt<<<(125 * 8192 + 255) / 256, 256>>>(w3b);
    k1_mma<<<(NV * HWSZ) / 128, 256, SMEM_K1>>>(img, wproj, bproj, bn1g, bn1b, bn1m, bn1v);
    k2_fuse<<<PP, 128>>>(xi, yi, valid);
    k3_mma<<<PP / 128, 256>>>(w3a, b3a, bn2g, bn2b, bn2m, bn2v);
    k4_mma<<<313, 128, SMEM_K4>>>(b3b, bn3g, bn3b, bn3m, bn3v);
    k5_head<<<PP / 256, 256>>>(w3c, b3c, out);
}